// round 7
// baseline (speedup 1.0000x reference)
#include <cuda_runtime.h>
#include <cuda_bf16.h>
#include <math.h>
#include <stdint.h>

// Problem constants
#define B   16
#define C   384
#define HD  8
#define DC  48
#define HW  4096
#define QC  192
#define KVC 768

#define NCHUNK_QK 8
#define NCHUNK_SV 16

// Scratch (device globals)
__device__ float g_kv [(long long)B * KVC * HW];
__device__ float g_q  [(long long)B * C   * HW];
__device__ float g_o  [(long long)B * C   * HW];
__device__ float g_Sp [NCHUNK_QK * B * HD * DC * DC];
__device__ float g_ssp[NCHUNK_QK * B * HD * 2 * DC];
__device__ float g_S  [B * HD * DC * DC];

// ---------------------------------------------------------------------------
// mma.sync helpers (sm_80-era PTX; valid on plain sm_100 target)
// ---------------------------------------------------------------------------
__device__ __forceinline__ uint32_t smem_u32(const void* p) {
    uint32_t a;
    asm("{ .reg .u64 t; cvta.to.shared.u64 t, %1; cvt.u32.u64 %0, t; }" : "=r"(a) : "l"(p));
    return a;
}
__device__ __forceinline__ void ldsm_x4(uint32_t r[4], uint32_t addr) {
    asm volatile("ldmatrix.sync.aligned.m8n8.x4.shared.b16 {%0,%1,%2,%3}, [%4];"
                 : "=r"(r[0]), "=r"(r[1]), "=r"(r[2]), "=r"(r[3]) : "r"(addr));
}
__device__ __forceinline__ void ldsm_x4_t(uint32_t r[4], uint32_t addr) {
    asm volatile("ldmatrix.sync.aligned.m8n8.x4.trans.shared.b16 {%0,%1,%2,%3}, [%4];"
                 : "=r"(r[0]), "=r"(r[1]), "=r"(r[2]), "=r"(r[3]) : "r"(addr));
}
__device__ __forceinline__ void mma_bf16(float* c, const uint32_t a[4],
                                         uint32_t b0, uint32_t b1) {
    asm volatile(
        "mma.sync.aligned.m16n8k16.row.col.f32.bf16.bf16.f32 "
        "{%0,%1,%2,%3}, {%4,%5,%6,%7}, {%8,%9}, {%0,%1,%2,%3};"
        : "+f"(c[0]), "+f"(c[1]), "+f"(c[2]), "+f"(c[3])
        : "r"(a[0]), "r"(a[1]), "r"(a[2]), "r"(a[3]), "r"(b0), "r"(b1));
}

// hi/lo bf16 split: x ~= hi + lo, each bf16 (8-bit mantissa) -> ~16 bit total
__device__ __forceinline__ void split_pack(float x0, float x1,
                                           uint32_t& ph, uint32_t& pl) {
    __nv_bfloat16 h0 = __float2bfloat16_rn(x0);
    __nv_bfloat16 h1 = __float2bfloat16_rn(x1);
    __nv_bfloat16 l0 = __float2bfloat16_rn(x0 - __bfloat162float(h0));
    __nv_bfloat16 l1 = __float2bfloat16_rn(x1 - __bfloat162float(h1));
    ph = (uint32_t)__bfloat16_as_ushort(h0) | ((uint32_t)__bfloat16_as_ushort(h1) << 16);
    pl = (uint32_t)__bfloat16_as_ushort(l0) | ((uint32_t)__bfloat16_as_ushort(l1) << 16);
}

// ---------------------------------------------------------------------------
// bf16-split tensor-core GEMM: Out[b][j][s] = sum_k W[j][k] * Act[b][k][s]
// CTA tile 128(j) x 128(s), K-chunk 32. 256 threads = 8 warps (4m x 2n),
// warp tile 32(j) x 64(s). out = Ah*Bh + Ah*Bl + Al*Bh.
// Software-pipelined: next chunk's LDGs issue before the MMA loop so DRAM
// latency hides under the 96-HMMA compute phase.
// ---------------------------------------------------------------------------
#define WPITCH 40    // bf16 elems per row of W tile (80B -> conflict-free ldmatrix)
#define APITCH 136   // bf16 elems per row of Act tile (272B -> conflict-free trans)

template<int K>
__global__ __launch_bounds__(256, 2) void gemm_bf16s_kernel(
    const float* __restrict__ W, const float* __restrict__ Act,
    float* __restrict__ Out, int OCtot)
{
    __shared__ __align__(16) uint16_t sWh[128 * WPITCH];
    __shared__ __align__(16) uint16_t sWl[128 * WPITCH];
    __shared__ __align__(16) uint16_t sAh[32 * APITCH];
    __shared__ __align__(16) uint16_t sAl[32 * APITCH];

    const int tid  = threadIdx.x;
    const int warp = tid >> 5;
    const int lane = tid & 31;
    const int s0 = blockIdx.x * 128;
    const int j0 = blockIdx.y * 128;
    const int b  = blockIdx.z;

    const float* Ap = Act + (long long)b * K * HW;
    float*       Op = Out + ((long long)b * OCtot + j0) * HW + s0;

    const int mbase = (warp >> 1) * 32;   // warp row base within tile
    const int nbase = (warp & 1) * 64;    // warp col base within tile

    const uint32_t uWh = smem_u32(sWh);
    const uint32_t uWl = smem_u32(sWl);
    const uint32_t uAh = smem_u32(sAh);
    const uint32_t uAl = smem_u32(sAl);

    float acc[64];
    #pragma unroll
    for (int i = 0; i < 64; i++) acc[i] = 0.f;

    // precomputed ldmatrix address components
    const int lrow = (lane & 7) + ((lane >> 3) & 1) * 8;   // row within 16-row block
    const int lhalf = lane >> 4;                           // 0/1: second 8-wide block

    // per-thread staging coordinates (fixed across chunks)
    const int wj = tid >> 1;             // W: row j (0..127)
    const int wq = (tid & 1) * 4;        // W: first of two q-slots (q, q+... step 2? see loop)
    const int akk = tid >> 5;            // A: k row base (0..7), +8 each i
    const int as4 = (tid & 31) * 4;      // A: spatial offset

    // ---- prefetch chunk 0 ----
    float4 wreg[4], areg[4];
    #pragma unroll
    for (int i = 0; i < 4; i++) {
        int idx = i * 256 + tid;
        int j = idx >> 3, q = idx & 7;
        wreg[i] = *(const float4*)&W[(long long)(j0 + j) * K + q * 4];
        int kk = idx >> 5, s4 = (idx & 31) * 4;
        areg[i] = *(const float4*)&Ap[(long long)kk * HW + s0 + s4];
    }

    for (int k0 = 0; k0 < K; k0 += 32) {
        // ---- split + store staged registers (chunk k0) ----
        #pragma unroll
        for (int i = 0; i < 4; i++) {
            int idx = i * 256 + tid;
            int j = idx >> 3, q = idx & 7;
            uint32_t h0, l0, h1, l1;
            split_pack(wreg[i].x, wreg[i].y, h0, l0);
            split_pack(wreg[i].z, wreg[i].w, h1, l1);
            *(uint2*)&sWh[j * WPITCH + q * 4] = make_uint2(h0, h1);
            *(uint2*)&sWl[j * WPITCH + q * 4] = make_uint2(l0, l1);
        }
        #pragma unroll
        for (int i = 0; i < 4; i++) {
            int idx = i * 256 + tid;
            int kk = idx >> 5, s4 = (idx & 31) * 4;
            uint32_t h0, l0, h1, l1;
            split_pack(areg[i].x, areg[i].y, h0, l0);
            split_pack(areg[i].z, areg[i].w, h1, l1);
            *(uint2*)&sAh[kk * APITCH + s4] = make_uint2(h0, h1);
            *(uint2*)&sAl[kk * APITCH + s4] = make_uint2(l0, l1);
        }
        __syncthreads();

        // ---- issue next chunk's LDGs (in flight during MMA loop) ----
        if (k0 + 32 < K) {
            const int kn = k0 + 32;
            #pragma unroll
            for (int i = 0; i < 4; i++) {
                int idx = i * 256 + tid;
                int j = idx >> 3, q = idx & 7;
                wreg[i] = *(const float4*)&W[(long long)(j0 + j) * K + kn + q * 4];
                int kk = idx >> 5, s4 = (idx & 31) * 4;
                areg[i] = *(const float4*)&Ap[(long long)(kn + kk) * HW + s0 + s4];
            }
        }

        // ---- MMA on staged chunk ----
        #pragma unroll
        for (int kh = 0; kh < 2; kh++) {
            uint32_t ah[2][4], al[2][4];
            #pragma unroll
            for (int mt = 0; mt < 2; mt++) {
                uint32_t off = (uint32_t)((mbase + mt * 16 + lrow) * (WPITCH * 2)
                                          + kh * 32 + lhalf * 16);
                ldsm_x4(ah[mt], uWh + off);
                ldsm_x4(al[mt], uWl + off);
            }
            #pragma unroll
            for (int np = 0; np < 4; np++) {
                uint32_t boff = (uint32_t)((kh * 16 + lrow) * (APITCH * 2)
                                           + (nbase + np * 16 + lhalf * 8) * 2);
                uint32_t bh[4], bl[4];
                ldsm_x4_t(bh, uAh + boff);
                ldsm_x4_t(bl, uAl + boff);
                #pragma unroll
                for (int nt2 = 0; nt2 < 2; nt2++) {
                    const uint32_t bh0 = bh[nt2 * 2], bh1 = bh[nt2 * 2 + 1];
                    const uint32_t bl0 = bl[nt2 * 2], bl1 = bl[nt2 * 2 + 1];
                    const int nt = np * 2 + nt2;
                    #pragma unroll
                    for (int mt = 0; mt < 2; mt++) {
                        float* cp = acc + (mt * 8 + nt) * 4;
                        mma_bf16(cp, ah[mt], bh0, bh1);
                        mma_bf16(cp, ah[mt], bl0, bl1);
                        mma_bf16(cp, al[mt], bh0, bh1);
                    }
                }
            }
        }
        __syncthreads();
    }

    // ---- epilogue ----
    const int crow = lane >> 2;
    const int ccol = (lane & 3) * 2;
    #pragma unroll
    for (int mt = 0; mt < 2; mt++) {
        #pragma unroll
        for (int nt = 0; nt < 8; nt++) {
            const float* cp = acc + (mt * 8 + nt) * 4;
            float* p = Op + (long long)(mbase + mt * 16 + crow) * HW
                          + nbase + nt * 8 + ccol;
            *(float2*)p            = make_float2(cp[0], cp[1]);
            *(float2*)(p + 8 * HW) = make_float2(cp[2], cp[3]);
        }
    }
}

// ---------------------------------------------------------------------------
// QK^T partials + sumsq partials. grid = (NCHUNK_QK, B*HD), 256 threads.
// ---------------------------------------------------------------------------
__global__ __launch_bounds__(256) void qk_partial_kernel(
    const float* __restrict__ qbuf, const float* __restrict__ kvbuf,
    float* __restrict__ Sp, float* __restrict__ ssp)
{
    const int chunk = blockIdx.x;
    const int bh = blockIdx.y;
    const int b  = bh >> 3;
    const int h  = bh & 7;
    const float* q = qbuf  + ((long long)b * C   + h * DC) * HW;
    const float* k = kvbuf + ((long long)b * KVC + h * DC) * HW;
    const int nbase = chunk * (HW / NCHUNK_QK);

    __shared__ float QsT[64][49];
    __shared__ float KsT[64][49];

    const int tid = threadIdx.x;
    const int tm = tid >> 4;
    const int tn = tid & 15;

    float acc[3][3] = {};
    float ssq = 0.f;

    for (int t = 0; t < (HW / NCHUNK_QK); t += 64) {
        const int n0 = nbase + t;
        for (int i = tid; i < DC * 64; i += 256) {
            int c  = i >> 6;
            int nn = i & 63;
            QsT[nn][c] = q[(long long)c * HW + n0 + nn];
            KsT[nn][c] = k[(long long)c * HW + n0 + nn];
        }
        __syncthreads();
        #pragma unroll 8
        for (int kk = 0; kk < 64; kk++) {
            float ra[3], rb[3];
            #pragma unroll
            for (int i = 0; i < 3; i++) ra[i] = QsT[kk][tm * 3 + i];
            #pragma unroll
            for (int j = 0; j < 3; j++) rb[j] = KsT[kk][tn * 3 + j];
            #pragma unroll
            for (int i = 0; i < 3; i++)
                #pragma unroll
                for (int j = 0; j < 3; j++)
                    acc[i][j] = fmaf(ra[i], rb[j], acc[i][j]);
        }
        if (tid < 2 * DC) {
            const int r = (tid < DC) ? tid : tid - DC;
            #pragma unroll 8
            for (int nn = 0; nn < 64; nn++) {
                float v = (tid < DC) ? QsT[nn][r] : KsT[nn][r];
                ssq = fmaf(v, v, ssq);
            }
        }
        __syncthreads();
    }

    float* Sout = Sp + ((long long)chunk * (B * HD) + bh) * (DC * DC);
    #pragma unroll
    for (int i = 0; i < 3; i++)
        #pragma unroll
        for (int j = 0; j < 3; j++)
            Sout[(tm * 3 + i) * DC + tn * 3 + j] = acc[i][j];

    if (tid < 2 * DC)
        ssp[((long long)chunk * (B * HD) + bh) * (2 * DC) + tid] = ssq;
}

// ---------------------------------------------------------------------------
// Reduce partials, apply norms + temperature, softmax. 128 blocks, 256 thr.
// ---------------------------------------------------------------------------
__global__ __launch_bounds__(256) void softmax_kernel(
    const float* __restrict__ Sp, const float* __restrict__ ssp,
    const float* __restrict__ temperature, float* __restrict__ Sout)
{
    const int bh = blockIdx.x;
    const int h  = bh & 7;
    const int tid = threadIdx.x;

    __shared__ float S[DC][DC + 1];
    __shared__ float invq[DC], invk[DC];

    for (int i = tid; i < DC * DC; i += 256) {
        float s = 0.f;
        #pragma unroll
        for (int ch = 0; ch < NCHUNK_QK; ch++)
            s += Sp[((long long)ch * (B * HD) + bh) * (DC * DC) + i];
        S[i / DC][i % DC] = s;
    }
    if (tid < 2 * DC) {
        float s = 0.f;
        #pragma unroll
        for (int ch = 0; ch < NCHUNK_QK; ch++)
            s += ssp[((long long)ch * (B * HD) + bh) * (2 * DC) + tid];
        float inv = 1.0f / fmaxf(sqrtf(s), 1e-12f);
        if (tid < DC) invq[tid] = inv; else invk[tid - DC] = inv;
    }
    __syncthreads();

    if (tid < DC) {
        const float t = temperature[h];
        const float iq = invq[tid] * t;
        float m = -INFINITY;
        float row[DC];
        #pragma unroll 8
        for (int d = 0; d < DC; d++) {
            float v = S[tid][d] * iq * invk[d];
            row[d] = v;
            m = fmaxf(m, v);
        }
        float sum = 0.f;
        #pragma unroll 8
        for (int d = 0; d < DC; d++) {
            float e = expf(row[d] - m);
            row[d] = e;
            sum += e;
        }
        float inv = 1.0f / sum;
        #pragma unroll 8
        for (int d = 0; d < DC; d++)
            Sout[(long long)bh * (DC * DC) + tid * DC + d] = row[d] * inv;
    }
}

// ---------------------------------------------------------------------------
// O = S * V, spatial-split. grid = (NCHUNK_SV, B*HD), 256 threads.
// ---------------------------------------------------------------------------
__global__ __launch_bounds__(256) void sv_kernel(
    const float* __restrict__ Sg, const float* __restrict__ kvbuf,
    float* __restrict__ obuf)
{
    const int chunk = blockIdx.x;
    const int bh = blockIdx.y;
    const int b  = bh >> 3;
    const int h  = bh & 7;
    const float* v = kvbuf + ((long long)b * KVC + C + h * DC) * HW;
    float*       o = obuf  + ((long long)b * C   + h * DC) * HW;
    const int nbase = chunk * (HW / NCHUNK_SV);

    __shared__ float S[DC][DC + 1];
    __shared__ float Vs[DC][68];

    const int tid = threadIdx.x;
    const int tm = tid >> 4;
    const int tn = tid & 15;
    const int tn4 = tn * 4;

    for (int i = tid; i < DC * DC; i += 256)
        S[i / DC][i % DC] = Sg[(long long)bh * (DC * DC) + i];
    __syncthreads();

    for (int t = 0; t < (HW / NCHUNK_SV); t += 64) {
        const int n0 = nbase + t;
        for (int i = tid; i < DC * 64; i += 256) {
            int d  = i >> 6;
            int nn = i & 63;
            Vs[d][nn] = v[(long long)d * HW + n0 + nn];
        }
        __syncthreads();
        float acc2[3][4] = {};
        #pragma unroll 4
        for (int d = 0; d < DC; d++) {
            float rs[3];
            #pragma unroll
            for (int i = 0; i < 3; i++) rs[i] = S[tm * 3 + i][d];
            float4 rv = *(const float4*)&Vs[d][tn4];
            #pragma unroll
            for (int i = 0; i < 3; i++) {
                acc2[i][0] = fmaf(rs[i], rv.x, acc2[i][0]);
                acc2[i][1] = fmaf(rs[i], rv.y, acc2[i][1]);
                acc2[i][2] = fmaf(rs[i], rv.z, acc2[i][2]);
                acc2[i][3] = fmaf(rs[i], rv.w, acc2[i][3]);
            }
        }
        #pragma unroll
        for (int i = 0; i < 3; i++) {
            *(float4*)&o[(long long)(tm * 3 + i) * HW + n0 + tn4] =
                make_float4(acc2[i][0], acc2[i][1], acc2[i][2], acc2[i][3]);
        }
        __syncthreads();
    }
}

// ---------------------------------------------------------------------------
// Launch
// ---------------------------------------------------------------------------
extern "C" void kernel_launch(void* const* d_in, const int* in_sizes, int n_in,
                              void* d_out, int out_size)
{
    const float* x           = (const float*)d_in[0];
    const float* query       = (const float*)d_in[1];
    const float* w_kv        = (const float*)d_in[2];
    const float* w_q         = (const float*)d_in[3];
    const float* w_proj      = (const float*)d_in[4];
    const float* temperature = (const float*)d_in[5];
    float* out = (float*)d_out;

    float *kv, *qb, *ob, *Sp, *ssp, *S;
    cudaGetSymbolAddress((void**)&kv,  g_kv);
    cudaGetSymbolAddress((void**)&qb,  g_q);
    cudaGetSymbolAddress((void**)&ob,  g_o);
    cudaGetSymbolAddress((void**)&Sp,  g_Sp);
    cudaGetSymbolAddress((void**)&ssp, g_ssp);
    cudaGetSymbolAddress((void**)&S,   g_S);

    // 1) kv = w_kv @ x        [768 x 384] x [384 x 4096] per batch
    gemm_bf16s_kernel<C><<<dim3(HW / 128, KVC / 128, B), 256>>>(w_kv, x, kv, KVC);

    // 2) q = w_q @ query      [384 x 192] x [192 x 4096] per batch
    gemm_bf16s_kernel<QC><<<dim3(HW / 128, C / 128, B), 256>>>(w_q, query, qb, C);

    // 3) QK^T partials + sumsq partials
    qk_partial_kernel<<<dim3(NCHUNK_QK, B * HD), 256>>>(qb, kv, Sp, ssp);

    // 4) reduce + norm-scale + softmax
    softmax_kernel<<<B * HD, 256>>>(Sp, ssp, temperature, S);

    // 5) O = S * V
    sv_kernel<<<dim3(NCHUNK_SV, B * HD), 256>>>(S, kv, ob);

    // 6) out = w_proj @ o     [384 x 384] x [384 x 4096] per batch
    gemm_bf16s_kernel<C><<<dim3(HW / 128, C / 128, B), 256>>>(w_proj, ob, out, C);
}

// round 8
// speedup vs baseline: 1.1218x; 1.1218x over previous
#include <cuda_runtime.h>
#include <cuda_bf16.h>
#include <math.h>
#include <stdint.h>

// Problem constants
#define B   16
#define C   384
#define HD  8
#define DC  48
#define HW  4096
#define QC  192
#define KVC 768

#define NCHUNK_QK 8
#define NCHUNK_SV 16

// Scratch (device globals)
__device__ float g_kv [(long long)B * KVC * HW];
__device__ float g_q  [(long long)B * C   * HW];
__device__ float g_Sp [NCHUNK_QK * B * HD * DC * DC];
__device__ float g_ssp[NCHUNK_QK * B * HD * 2 * DC];
__device__ float g_S  [B * HD * DC * DC];

// Pre-split bf16 hi/lo operands
__device__ __nv_bfloat16 g_wkvh[KVC * C],  g_wkvl[KVC * C];
__device__ __nv_bfloat16 g_wqh [C * QC],   g_wql [C * QC];
__device__ __nv_bfloat16 g_wph [C * C],    g_wpl [C * C];
__device__ __nv_bfloat16 g_xh [(long long)B * C  * HW], g_xl [(long long)B * C  * HW];
__device__ __nv_bfloat16 g_qrh[(long long)B * QC * HW], g_qrl[(long long)B * QC * HW];
__device__ __nv_bfloat16 g_oh [(long long)B * C  * HW], g_ol [(long long)B * C  * HW];

// ---------------------------------------------------------------------------
// PTX helpers
// ---------------------------------------------------------------------------
__device__ __forceinline__ uint32_t smem_u32(const void* p) {
    uint32_t a;
    asm("{ .reg .u64 t; cvta.to.shared.u64 t, %1; cvt.u32.u64 %0, t; }" : "=r"(a) : "l"(p));
    return a;
}
__device__ __forceinline__ void cp16(uint32_t dst, const void* src) {
    asm volatile("cp.async.ca.shared.global [%0], [%1], 16;" :: "r"(dst), "l"(src));
}
#define CP_COMMIT() asm volatile("cp.async.commit_group;" ::: "memory")
#define CP_WAIT0()  asm volatile("cp.async.wait_group 0;" ::: "memory")

__device__ __forceinline__ void ldsm_x4(uint32_t r[4], uint32_t addr) {
    asm volatile("ldmatrix.sync.aligned.m8n8.x4.shared.b16 {%0,%1,%2,%3}, [%4];"
                 : "=r"(r[0]), "=r"(r[1]), "=r"(r[2]), "=r"(r[3]) : "r"(addr));
}
__device__ __forceinline__ void ldsm_x4_t(uint32_t r[4], uint32_t addr) {
    asm volatile("ldmatrix.sync.aligned.m8n8.x4.trans.shared.b16 {%0,%1,%2,%3}, [%4];"
                 : "=r"(r[0]), "=r"(r[1]), "=r"(r[2]), "=r"(r[3]) : "r"(addr));
}
__device__ __forceinline__ void mma_bf16(float* c, const uint32_t a[4],
                                         uint32_t b0, uint32_t b1) {
    asm volatile(
        "mma.sync.aligned.m16n8k16.row.col.f32.bf16.bf16.f32 "
        "{%0,%1,%2,%3}, {%4,%5,%6,%7}, {%8,%9}, {%0,%1,%2,%3};"
        : "+f"(c[0]), "+f"(c[1]), "+f"(c[2]), "+f"(c[3])
        : "r"(a[0]), "r"(a[1]), "r"(a[2]), "r"(a[3]), "r"(b0), "r"(b1));
}

// hi/lo bf16 split: x ~= hi + lo
__device__ __forceinline__ void split_pack(float x0, float x1,
                                           uint32_t& ph, uint32_t& pl) {
    __nv_bfloat16 h0 = __float2bfloat16_rn(x0);
    __nv_bfloat16 h1 = __float2bfloat16_rn(x1);
    __nv_bfloat16 l0 = __float2bfloat16_rn(x0 - __bfloat162float(h0));
    __nv_bfloat16 l1 = __float2bfloat16_rn(x1 - __bfloat162float(h1));
    ph = (uint32_t)__bfloat16_as_ushort(h0) | ((uint32_t)__bfloat16_as_ushort(h1) << 16);
    pl = (uint32_t)__bfloat16_as_ushort(l0) | ((uint32_t)__bfloat16_as_ushort(l1) << 16);
}

// ---------------------------------------------------------------------------
// Generic fp32 -> bf16 hi/lo pre-split. One float4 per thread.
// ---------------------------------------------------------------------------
__global__ __launch_bounds__(256) void split_kernel(
    const float* __restrict__ src, __nv_bfloat16* __restrict__ dh,
    __nv_bfloat16* __restrict__ dl, int n4)
{
    int i = blockIdx.x * 256 + threadIdx.x;
    if (i < n4) {
        float4 v = ((const float4*)src)[i];
        uint32_t h0, l0, h1, l1;
        split_pack(v.x, v.y, h0, l0);
        split_pack(v.z, v.w, h1, l1);
        ((uint2*)dh)[i] = make_uint2(h0, h1);
        ((uint2*)dl)[i] = make_uint2(l0, l1);
    }
}

// ---------------------------------------------------------------------------
// bf16-split tensor-core GEMM on PRE-SPLIT operands:
//   Out[b][j][s] = sum_k W[j][k] * Act[b][k][s], out = Ah*Bh + Ah*Bl + Al*Bh
// CTA tile 128(j) x 128(s), K-chunk 32, 8 warps (4m x 2n), warp 32x64.
// Staging = pure cp.async copies (no conversions in the hot loop).
// ---------------------------------------------------------------------------
#define WPITCH 40    // bf16/row of W tile (80B -> conflict-free ldmatrix)
#define APITCH 136   // bf16/row of Act tile (272B -> conflict-free trans)

template<int K>
__global__ __launch_bounds__(256, 2) void gemm_pre_kernel(
    const __nv_bfloat16* __restrict__ Wh, const __nv_bfloat16* __restrict__ Wl,
    const __nv_bfloat16* __restrict__ Ah, const __nv_bfloat16* __restrict__ Al,
    float* __restrict__ Out, int OCtot)
{
    __shared__ __align__(16) uint16_t sWh[128 * WPITCH];
    __shared__ __align__(16) uint16_t sWl[128 * WPITCH];
    __shared__ __align__(16) uint16_t sAh[32 * APITCH];
    __shared__ __align__(16) uint16_t sAl[32 * APITCH];

    const int tid  = threadIdx.x;
    const int warp = tid >> 5;
    const int lane = tid & 31;
    const int s0 = blockIdx.x * 128;
    const int j0 = blockIdx.y * 128;
    const int b  = blockIdx.z;

    const __nv_bfloat16* Aph = Ah + (long long)b * K * HW;
    const __nv_bfloat16* Apl = Al + (long long)b * K * HW;
    float* Op = Out + ((long long)b * OCtot + j0) * HW + s0;

    const int mbase = (warp >> 1) * 32;
    const int nbase = (warp & 1) * 64;

    const uint32_t uWh = smem_u32(sWh);
    const uint32_t uWl = smem_u32(sWl);
    const uint32_t uAh = smem_u32(sAh);
    const uint32_t uAl = smem_u32(sAl);

    float acc[64];
    #pragma unroll
    for (int i = 0; i < 64; i++) acc[i] = 0.f;

    const int lrow  = (lane & 7) + ((lane >> 3) & 1) * 8;
    const int lhalf = lane >> 4;

    for (int k0 = 0; k0 < K; k0 += 32) {
        // ---- stage via cp.async: pure 16B copies ----
        // W tiles: 128 rows x 32 bf16 = 512 x 16B per array, 2 per thread
        #pragma unroll
        for (int i = 0; i < 2; i++) {
            int idx = i * 256 + tid;
            int j = idx >> 2, q = idx & 3;        // q: 8-bf16 group in row
            uint32_t d = (uint32_t)(j * WPITCH + q * 8) * 2;
            long long g = (long long)(j0 + j) * K + k0 + q * 8;
            cp16(uWh + d, Wh + g);
            cp16(uWl + d, Wl + g);
        }
        // Act tiles: 32 rows x 128 bf16 = 512 x 16B per array, 2 per thread
        #pragma unroll
        for (int i = 0; i < 2; i++) {
            int idx = i * 256 + tid;
            int kk = idx >> 4, g8 = idx & 15;
            uint32_t d = (uint32_t)(kk * APITCH + g8 * 8) * 2;
            long long g = (long long)(k0 + kk) * HW + s0 + g8 * 8;
            cp16(uAh + d, Aph + g);
            cp16(uAl + d, Apl + g);
        }
        CP_COMMIT();
        CP_WAIT0();
        __syncthreads();

        // ---- MMA on staged chunk ----
        #pragma unroll
        for (int kh = 0; kh < 2; kh++) {
            uint32_t ah[2][4], al[2][4];
            #pragma unroll
            for (int mt = 0; mt < 2; mt++) {
                uint32_t off = (uint32_t)((mbase + mt * 16 + lrow) * (WPITCH * 2)
                                          + kh * 32 + lhalf * 16);
                ldsm_x4(ah[mt], uWh + off);
                ldsm_x4(al[mt], uWl + off);
            }
            #pragma unroll
            for (int np = 0; np < 4; np++) {
                uint32_t boff = (uint32_t)((kh * 16 + lrow) * (APITCH * 2)
                                           + (nbase + np * 16 + lhalf * 8) * 2);
                uint32_t bh[4], bl[4];
                ldsm_x4_t(bh, uAh + boff);
                ldsm_x4_t(bl, uAl + boff);
                #pragma unroll
                for (int nt2 = 0; nt2 < 2; nt2++) {
                    const uint32_t bh0 = bh[nt2 * 2], bh1 = bh[nt2 * 2 + 1];
                    const uint32_t bl0 = bl[nt2 * 2], bl1 = bl[nt2 * 2 + 1];
                    const int nt = np * 2 + nt2;
                    #pragma unroll
                    for (int mt = 0; mt < 2; mt++) {
                        float* cp = acc + (mt * 8 + nt) * 4;
                        mma_bf16(cp, ah[mt], bh0, bh1);
                        mma_bf16(cp, ah[mt], bl0, bl1);
                        mma_bf16(cp, al[mt], bh0, bh1);
                    }
                }
            }
        }
        __syncthreads();
    }

    // ---- epilogue (fp32 stores) ----
    const int crow = lane >> 2;
    const int ccol = (lane & 3) * 2;
    #pragma unroll
    for (int mt = 0; mt < 2; mt++) {
        #pragma unroll
        for (int nt = 0; nt < 8; nt++) {
            const float* cp = acc + (mt * 8 + nt) * 4;
            float* p = Op + (long long)(mbase + mt * 16 + crow) * HW
                          + nbase + nt * 8 + ccol;
            *(float2*)p            = make_float2(cp[0], cp[1]);
            *(float2*)(p + 8 * HW) = make_float2(cp[2], cp[3]);
        }
    }
}

// ---------------------------------------------------------------------------
// QK^T partials + sumsq partials. grid = (NCHUNK_QK, B*HD), 256 threads.
// ---------------------------------------------------------------------------
__global__ __launch_bounds__(256) void qk_partial_kernel(
    const float* __restrict__ qbuf, const float* __restrict__ kvbuf,
    float* __restrict__ Sp, float* __restrict__ ssp)
{
    const int chunk = blockIdx.x;
    const int bh = blockIdx.y;
    const int b  = bh >> 3;
    const int h  = bh & 7;
    const float* q = qbuf  + ((long long)b * C   + h * DC) * HW;
    const float* k = kvbuf + ((long long)b * KVC + h * DC) * HW;
    const int nbase = chunk * (HW / NCHUNK_QK);

    __shared__ float QsT[64][49];
    __shared__ float KsT[64][49];

    const int tid = threadIdx.x;
    const int tm = tid >> 4;
    const int tn = tid & 15;

    float acc[3][3] = {};
    float ssq = 0.f;

    for (int t = 0; t < (HW / NCHUNK_QK); t += 64) {
        const int n0 = nbase + t;
        for (int i = tid; i < DC * 64; i += 256) {
            int c  = i >> 6;
            int nn = i & 63;
            QsT[nn][c] = q[(long long)c * HW + n0 + nn];
            KsT[nn][c] = k[(long long)c * HW + n0 + nn];
        }
        __syncthreads();
        #pragma unroll 8
        for (int kk = 0; kk < 64; kk++) {
            float ra[3], rb[3];
            #pragma unroll
            for (int i = 0; i < 3; i++) ra[i] = QsT[kk][tm * 3 + i];
            #pragma unroll
            for (int j = 0; j < 3; j++) rb[j] = KsT[kk][tn * 3 + j];
            #pragma unroll
            for (int i = 0; i < 3; i++)
                #pragma unroll
                for (int j = 0; j < 3; j++)
                    acc[i][j] = fmaf(ra[i], rb[j], acc[i][j]);
        }
        if (tid < 2 * DC) {
            const int r = (tid < DC) ? tid : tid - DC;
            #pragma unroll 8
            for (int nn = 0; nn < 64; nn++) {
                float v = (tid < DC) ? QsT[nn][r] : KsT[nn][r];
                ssq = fmaf(v, v, ssq);
            }
        }
        __syncthreads();
    }

    float* Sout = Sp + ((long long)chunk * (B * HD) + bh) * (DC * DC);
    #pragma unroll
    for (int i = 0; i < 3; i++)
        #pragma unroll
        for (int j = 0; j < 3; j++)
            Sout[(tm * 3 + i) * DC + tn * 3 + j] = acc[i][j];

    if (tid < 2 * DC)
        ssp[((long long)chunk * (B * HD) + bh) * (2 * DC) + tid] = ssq;
}

// ---------------------------------------------------------------------------
// Reduce partials, apply norms + temperature, softmax. 128 blocks, 256 thr.
// ---------------------------------------------------------------------------
__global__ __launch_bounds__(256) void softmax_kernel(
    const float* __restrict__ Sp, const float* __restrict__ ssp,
    const float* __restrict__ temperature, float* __restrict__ Sout)
{
    const int bh = blockIdx.x;
    const int h  = bh & 7;
    const int tid = threadIdx.x;

    __shared__ float S[DC][DC + 1];
    __shared__ float invq[DC], invk[DC];

    for (int i = tid; i < DC * DC; i += 256) {
        float s = 0.f;
        #pragma unroll
        for (int ch = 0; ch < NCHUNK_QK; ch++)
            s += Sp[((long long)ch * (B * HD) + bh) * (DC * DC) + i];
        S[i / DC][i % DC] = s;
    }
    if (tid < 2 * DC) {
        float s = 0.f;
        #pragma unroll
        for (int ch = 0; ch < NCHUNK_QK; ch++)
            s += ssp[((long long)ch * (B * HD) + bh) * (2 * DC) + tid];
        float inv = 1.0f / fmaxf(sqrtf(s), 1e-12f);
        if (tid < DC) invq[tid] = inv; else invk[tid - DC] = inv;
    }
    __syncthreads();

    if (tid < DC) {
        const float t = temperature[h];
        const float iq = invq[tid] * t;
        float m = -INFINITY;
        float row[DC];
        #pragma unroll 8
        for (int d = 0; d < DC; d++) {
            float v = S[tid][d] * iq * invk[d];
            row[d] = v;
            m = fmaxf(m, v);
        }
        float sum = 0.f;
        #pragma unroll 8
        for (int d = 0; d < DC; d++) {
            float e = expf(row[d] - m);
            row[d] = e;
            sum += e;
        }
        float inv = 1.0f / sum;
        #pragma unroll 8
        for (int d = 0; d < DC; d++)
            Sout[(long long)bh * (DC * DC) + tid * DC + d] = row[d] * inv;
    }
}

// ---------------------------------------------------------------------------
// O = S * V, spatial-split. Writes hi/lo bf16 (pre-split for GEMM3).
// grid = (NCHUNK_SV, B*HD), 256 threads.
// ---------------------------------------------------------------------------
__global__ __launch_bounds__(256) void sv_kernel(
    const float* __restrict__ Sg, const float* __restrict__ kvbuf,
    __nv_bfloat16* __restrict__ oh, __nv_bfloat16* __restrict__ ol)
{
    const int chunk = blockIdx.x;
    const int bh = blockIdx.y;
    const int b  = bh >> 3;
    const int h  = bh & 7;
    const float* v = kvbuf + ((long long)b * KVC + C + h * DC) * HW;
    const long long obase = ((long long)b * C + h * DC) * HW;
    const int nbase = chunk * (HW / NCHUNK_SV);

    __shared__ float S[DC][DC + 1];
    __shared__ float Vs[DC][68];

    const int tid = threadIdx.x;
    const int tm = tid >> 4;
    const int tn = tid & 15;
    const int tn4 = tn * 4;

    for (int i = tid; i < DC * DC; i += 256)
        S[i / DC][i % DC] = Sg[(long long)bh * (DC * DC) + i];
    __syncthreads();

    for (int t = 0; t < (HW / NCHUNK_SV); t += 64) {
        const int n0 = nbase + t;
        for (int i = tid; i < DC * 64; i += 256) {
            int d  = i >> 6;
            int nn = i & 63;
            Vs[d][nn] = v[(long long)d * HW + n0 + nn];
        }
        __syncthreads();
        float acc2[3][4] = {};
        #pragma unroll 4
        for (int d = 0; d < DC; d++) {
            float rs[3];
            #pragma unroll
            for (int i = 0; i < 3; i++) rs[i] = S[tm * 3 + i][d];
            float4 rv = *(const float4*)&Vs[d][tn4];
            #pragma unroll
            for (int i = 0; i < 3; i++) {
                acc2[i][0] = fmaf(rs[i], rv.x, acc2[i][0]);
                acc2[i][1] = fmaf(rs[i], rv.y, acc2[i][1]);
                acc2[i][2] = fmaf(rs[i], rv.z, acc2[i][2]);
                acc2[i][3] = fmaf(rs[i], rv.w, acc2[i][3]);
            }
        }
        #pragma unroll
        for (int i = 0; i < 3; i++) {
            long long off = obase + (long long)(tm * 3 + i) * HW + n0 + tn4;
            uint32_t h0, l0, h1, l1;
            split_pack(acc2[i][0], acc2[i][1], h0, l0);
            split_pack(acc2[i][2], acc2[i][3], h1, l1);
            *(uint2*)&oh[off] = make_uint2(h0, h1);
            *(uint2*)&ol[off] = make_uint2(l0, l1);
        }
        __syncthreads();
    }
}

// ---------------------------------------------------------------------------
// Launch
// ---------------------------------------------------------------------------
extern "C" void kernel_launch(void* const* d_in, const int* in_sizes, int n_in,
                              void* d_out, int out_size)
{
    const float* x           = (const float*)d_in[0];
    const float* query       = (const float*)d_in[1];
    const float* w_kv        = (const float*)d_in[2];
    const float* w_q         = (const float*)d_in[3];
    const float* w_proj      = (const float*)d_in[4];
    const float* temperature = (const float*)d_in[5];
    float* out = (float*)d_out;

    float *kv, *qb, *Sp, *ssp, *S;
    cudaGetSymbolAddress((void**)&kv,  g_kv);
    cudaGetSymbolAddress((void**)&qb,  g_q);
    cudaGetSymbolAddress((void**)&Sp,  g_Sp);
    cudaGetSymbolAddress((void**)&ssp, g_ssp);
    cudaGetSymbolAddress((void**)&S,   g_S);

    __nv_bfloat16 *wkvh, *wkvl, *wqh, *wql, *wph, *wpl, *xh, *xl, *qrh, *qrl, *oh, *ol;
    cudaGetSymbolAddress((void**)&wkvh, g_wkvh);
    cudaGetSymbolAddress((void**)&wkvl, g_wkvl);
    cudaGetSymbolAddress((void**)&wqh,  g_wqh);
    cudaGetSymbolAddress((void**)&wql,  g_wql);
    cudaGetSymbolAddress((void**)&wph,  g_wph);
    cudaGetSymbolAddress((void**)&wpl,  g_wpl);
    cudaGetSymbolAddress((void**)&xh,   g_xh);
    cudaGetSymbolAddress((void**)&xl,   g_xl);
    cudaGetSymbolAddress((void**)&qrh,  g_qrh);
    cudaGetSymbolAddress((void**)&qrl,  g_qrl);
    cudaGetSymbolAddress((void**)&oh,   g_oh);
    cudaGetSymbolAddress((void**)&ol,   g_ol);

    // 0) pre-split all GEMM inputs into bf16 hi/lo
    {
        int n4;
        n4 = KVC * C / 4;
        split_kernel<<<(n4 + 255) / 256, 256>>>(w_kv, wkvh, wkvl, n4);
        n4 = C * QC / 4;
        split_kernel<<<(n4 + 255) / 256, 256>>>(w_q, wqh, wql, n4);
        n4 = C * C / 4;
        split_kernel<<<(n4 + 255) / 256, 256>>>(w_proj, wph, wpl, n4);
        n4 = (int)((long long)B * C * HW / 4);
        split_kernel<<<(n4 + 255) / 256, 256>>>(x, xh, xl, n4);
        n4 = (int)((long long)B * QC * HW / 4);
        split_kernel<<<(n4 + 255) / 256, 256>>>(query, qrh, qrl, n4);
    }

    // 1) kv = w_kv @ x        [768 x 384] x [384 x 4096] per batch
    gemm_pre_kernel<C><<<dim3(HW / 128, KVC / 128, B), 256>>>(
        wkvh, wkvl, xh, xl, kv, KVC);

    // 2) q = w_q @ query      [384 x 192] x [192 x 4096] per batch
    gemm_pre_kernel<QC><<<dim3(HW / 128, C / 128, B), 256>>>(
        wqh, wql, qrh, qrl, qb, C);

    // 3) QK^T partials + sumsq partials
    qk_partial_kernel<<<dim3(NCHUNK_QK, B * HD), 256>>>(qb, kv, Sp, ssp);

    // 4) reduce + norm-scale + softmax
    softmax_kernel<<<B * HD, 256>>>(Sp, ssp, temperature, S);

    // 5) O = S * V (writes pre-split hi/lo)
    sv_kernel<<<dim3(NCHUNK_SV, B * HD), 256>>>(S, kv, oh, ol);

    // 6) out = w_proj @ o     [384 x 384] x [384 x 4096] per batch
    gemm_pre_kernel<C><<<dim3(HW / 128, C / 128, B), 256>>>(
        wph, wpl, oh, ol, out, C);
}

// round 9
// speedup vs baseline: 1.1347x; 1.0115x over previous
#include <cuda_runtime.h>
#include <cuda_bf16.h>
#include <math.h>
#include <stdint.h>

// Problem constants
#define B   16
#define C   384
#define HD  8
#define DC  48
#define HW  4096
#define QC  192
#define KVC 768

#define NCHUNK_QK 8
#define NCHUNK_SV 16

// Scratch (device globals)
__device__ float g_kv [(long long)B * KVC * HW];
__device__ float g_q  [(long long)B * C   * HW];
__device__ float g_Sp [NCHUNK_QK * B * HD * DC * DC];
__device__ float g_ssp[NCHUNK_QK * B * HD * 2 * DC];
__device__ float g_S  [B * HD * DC * DC];

// Pre-split bf16 hi/lo operands
__device__ __nv_bfloat16 g_wkvh[KVC * C],  g_wkvl[KVC * C];
__device__ __nv_bfloat16 g_wqh [C * QC],   g_wql [C * QC];
__device__ __nv_bfloat16 g_wph [C * C],    g_wpl [C * C];
__device__ __nv_bfloat16 g_xh [(long long)B * C  * HW], g_xl [(long long)B * C  * HW];
__device__ __nv_bfloat16 g_qrh[(long long)B * QC * HW], g_qrl[(long long)B * QC * HW];
__device__ __nv_bfloat16 g_oh [(long long)B * C  * HW], g_ol [(long long)B * C  * HW];

// ---------------------------------------------------------------------------
// PTX helpers
// ---------------------------------------------------------------------------
__device__ __forceinline__ uint32_t smem_u32(const void* p) {
    uint32_t a;
    asm("{ .reg .u64 t; cvta.to.shared.u64 t, %1; cvt.u32.u64 %0, t; }" : "=r"(a) : "l"(p));
    return a;
}
__device__ __forceinline__ void cp16(uint32_t dst, const void* src) {
    asm volatile("cp.async.ca.shared.global [%0], [%1], 16;" :: "r"(dst), "l"(src));
}
#define CP_COMMIT() asm volatile("cp.async.commit_group;" ::: "memory")
#define CP_WAIT0()  asm volatile("cp.async.wait_group 0;" ::: "memory")
#define CP_WAIT1()  asm volatile("cp.async.wait_group 1;" ::: "memory")

__device__ __forceinline__ void ldsm_x4(uint32_t r[4], uint32_t addr) {
    asm volatile("ldmatrix.sync.aligned.m8n8.x4.shared.b16 {%0,%1,%2,%3}, [%4];"
                 : "=r"(r[0]), "=r"(r[1]), "=r"(r[2]), "=r"(r[3]) : "r"(addr));
}
__device__ __forceinline__ void ldsm_x4_t(uint32_t r[4], uint32_t addr) {
    asm volatile("ldmatrix.sync.aligned.m8n8.x4.trans.shared.b16 {%0,%1,%2,%3}, [%4];"
                 : "=r"(r[0]), "=r"(r[1]), "=r"(r[2]), "=r"(r[3]) : "r"(addr));
}
__device__ __forceinline__ void mma_bf16(float* c, const uint32_t a[4],
                                         uint32_t b0, uint32_t b1) {
    asm volatile(
        "mma.sync.aligned.m16n8k16.row.col.f32.bf16.bf16.f32 "
        "{%0,%1,%2,%3}, {%4,%5,%6,%7}, {%8,%9}, {%0,%1,%2,%3};"
        : "+f"(c[0]), "+f"(c[1]), "+f"(c[2]), "+f"(c[3])
        : "r"(a[0]), "r"(a[1]), "r"(a[2]), "r"(a[3]), "r"(b0), "r"(b1));
}

// hi/lo bf16 split: x ~= hi + lo
__device__ __forceinline__ void split_pack(float x0, float x1,
                                           uint32_t& ph, uint32_t& pl) {
    __nv_bfloat16 h0 = __float2bfloat16_rn(x0);
    __nv_bfloat16 h1 = __float2bfloat16_rn(x1);
    __nv_bfloat16 l0 = __float2bfloat16_rn(x0 - __bfloat162float(h0));
    __nv_bfloat16 l1 = __float2bfloat16_rn(x1 - __bfloat162float(h1));
    ph = (uint32_t)__bfloat16_as_ushort(h0) | ((uint32_t)__bfloat16_as_ushort(h1) << 16);
    pl = (uint32_t)__bfloat16_as_ushort(l0) | ((uint32_t)__bfloat16_as_ushort(l1) << 16);
}

// ---------------------------------------------------------------------------
// Generic fp32 -> bf16 hi/lo pre-split. One float4 per thread.
// ---------------------------------------------------------------------------
__global__ __launch_bounds__(256) void split_kernel(
    const float* __restrict__ src, __nv_bfloat16* __restrict__ dh,
    __nv_bfloat16* __restrict__ dl, int n4)
{
    int i = blockIdx.x * 256 + threadIdx.x;
    if (i < n4) {
        float4 v = ((const float4*)src)[i];
        uint32_t h0, l0, h1, l1;
        split_pack(v.x, v.y, h0, l0);
        split_pack(v.z, v.w, h1, l1);
        ((uint2*)dh)[i] = make_uint2(h0, h1);
        ((uint2*)dl)[i] = make_uint2(l0, l1);
    }
}

// ---------------------------------------------------------------------------
// Double-buffered bf16-split tensor-core GEMM on pre-split operands:
//   Out[b][j][s] = sum_k W[j][k] * Act[b][k][s], out = Ah*Bh + Ah*Bl + Al*Bh
// CTA tile 128(j) x 128(s), K-chunk 32, 8 warps (4m x 2n), warp 32x64.
// cp.async pipeline: chunk k+1 staged while chunk k computes.
// ---------------------------------------------------------------------------
#define WPITCH 40    // bf16/row of W tile (80B -> conflict-free ldmatrix)
#define APITCH 136   // bf16/row of Act tile (272B -> conflict-free trans)

#define WTE (128 * WPITCH)           // uint16 elems per W array
#define ATE (32 * APITCH)            // uint16 elems per A array
#define BUFE (2 * WTE + 2 * ATE)     // per-buffer elems (18944)
#define SMEM_BYTES (2 * BUFE * 2)    // 75776 bytes

template<int K>
__global__ __launch_bounds__(256, 2) void gemm_db_kernel(
    const __nv_bfloat16* __restrict__ Wh, const __nv_bfloat16* __restrict__ Wl,
    const __nv_bfloat16* __restrict__ Ah, const __nv_bfloat16* __restrict__ Al,
    float* __restrict__ Out, int OCtot)
{
    extern __shared__ __align__(16) uint16_t dynsmem[];
    const uint32_t uS = smem_u32(dynsmem);

    const int tid  = threadIdx.x;
    const int warp = tid >> 5;
    const int lane = tid & 31;
    const int s0 = blockIdx.x * 128;
    const int j0 = blockIdx.y * 128;
    const int b  = blockIdx.z;

    const __nv_bfloat16* Aph = Ah + (long long)b * K * HW;
    const __nv_bfloat16* Apl = Al + (long long)b * K * HW;
    float* Op = Out + ((long long)b * OCtot + j0) * HW + s0;

    const int mbase = (warp >> 1) * 32;
    const int nbase = (warp & 1) * 64;

    float acc[64];
    #pragma unroll
    for (int i = 0; i < 64; i++) acc[i] = 0.f;

    const int lrow  = (lane & 7) + ((lane >> 3) & 1) * 8;
    const int lhalf = lane >> 4;

    // staging coordinates (fixed per thread)
    const int wj = tid >> 2, wq = tid & 3;          // + i*64 rows
    const int ak = tid >> 4, ag = tid & 15;         // + i*16 k-rows

    auto stage = [&](int kc, int buf) {
        const uint32_t bWh = uS + (uint32_t)(buf * BUFE) * 2;
        const uint32_t bWl = bWh + WTE * 2;
        const uint32_t bAh = bWl + WTE * 2;
        const uint32_t bAl = bAh + ATE * 2;
        const int k0 = kc * 32;
        #pragma unroll
        for (int i = 0; i < 2; i++) {
            int j = wj + i * 64;
            uint32_t d = (uint32_t)(j * WPITCH + wq * 8) * 2;
            long long g = (long long)(j0 + j) * K + k0 + wq * 8;
            cp16(bWh + d, Wh + g);
            cp16(bWl + d, Wl + g);
        }
        #pragma unroll
        for (int i = 0; i < 2; i++) {
            int kk = ak + i * 16;
            uint32_t d = (uint32_t)(kk * APITCH + ag * 8) * 2;
            long long g = (long long)(k0 + kk) * HW + s0 + ag * 8;
            cp16(bAh + d, Aph + g);
            cp16(bAl + d, Apl + g);
        }
        CP_COMMIT();
    };

    const int NK = K / 32;
    stage(0, 0);

    for (int kc = 0; kc < NK; kc++) {
        const int buf = kc & 1;
        if (kc + 1 < NK) {
            stage(kc + 1, (kc + 1) & 1);
            CP_WAIT1();          // chunk kc complete; kc+1 still in flight
        } else {
            CP_WAIT0();
        }
        __syncthreads();

        const uint32_t bWh = uS + (uint32_t)(buf * BUFE) * 2;
        const uint32_t bWl = bWh + WTE * 2;
        const uint32_t bAh = bWl + WTE * 2;
        const uint32_t bAl = bAh + ATE * 2;

        #pragma unroll
        for (int kh = 0; kh < 2; kh++) {
            uint32_t ah[2][4], al[2][4];
            #pragma unroll
            for (int mt = 0; mt < 2; mt++) {
                uint32_t off = (uint32_t)((mbase + mt * 16 + lrow) * (WPITCH * 2)
                                          + kh * 32 + lhalf * 16);
                ldsm_x4(ah[mt], bWh + off);
                ldsm_x4(al[mt], bWl + off);
            }
            #pragma unroll
            for (int np = 0; np < 4; np++) {
                uint32_t boff = (uint32_t)((kh * 16 + lrow) * (APITCH * 2)
                                           + (nbase + np * 16 + lhalf * 8) * 2);
                uint32_t bh[4], bl[4];
                ldsm_x4_t(bh, bAh + boff);
                ldsm_x4_t(bl, bAl + boff);
                #pragma unroll
                for (int nt2 = 0; nt2 < 2; nt2++) {
                    const uint32_t bh0 = bh[nt2 * 2], bh1 = bh[nt2 * 2 + 1];
                    const uint32_t bl0 = bl[nt2 * 2], bl1 = bl[nt2 * 2 + 1];
                    const int nt = np * 2 + nt2;
                    #pragma unroll
                    for (int mt = 0; mt < 2; mt++) {
                        float* cp = acc + (mt * 8 + nt) * 4;
                        mma_bf16(cp, ah[mt], bh0, bh1);
                        mma_bf16(cp, ah[mt], bl0, bl1);
                        mma_bf16(cp, al[mt], bh0, bh1);
                    }
                }
            }
        }
        __syncthreads();   // all reads of buf done before it is restaged
    }

    // ---- epilogue (fp32 stores) ----
    const int crow = lane >> 2;
    const int ccol = (lane & 3) * 2;
    #pragma unroll
    for (int mt = 0; mt < 2; mt++) {
        #pragma unroll
        for (int nt = 0; nt < 8; nt++) {
            const float* cp = acc + (mt * 8 + nt) * 4;
            float* p = Op + (long long)(mbase + mt * 16 + crow) * HW
                          + nbase + nt * 8 + ccol;
            *(float2*)p            = make_float2(cp[0], cp[1]);
            *(float2*)(p + 8 * HW) = make_float2(cp[2], cp[3]);
        }
    }
}

// ---------------------------------------------------------------------------
// QK^T partials + sumsq partials. grid = (NCHUNK_QK, B*HD), 256 threads.
// ---------------------------------------------------------------------------
__global__ __launch_bounds__(256) void qk_partial_kernel(
    const float* __restrict__ qbuf, const float* __restrict__ kvbuf,
    float* __restrict__ Sp, float* __restrict__ ssp)
{
    const int chunk = blockIdx.x;
    const int bh = blockIdx.y;
    const int b  = bh >> 3;
    const int h  = bh & 7;
    const float* q = qbuf  + ((long long)b * C   + h * DC) * HW;
    const float* k = kvbuf + ((long long)b * KVC + h * DC) * HW;
    const int nbase = chunk * (HW / NCHUNK_QK);

    __shared__ float QsT[64][49];
    __shared__ float KsT[64][49];

    const int tid = threadIdx.x;
    const int tm = tid >> 4;
    const int tn = tid & 15;

    float acc[3][3] = {};
    float ssq = 0.f;

    for (int t = 0; t < (HW / NCHUNK_QK); t += 64) {
        const int n0 = nbase + t;
        for (int i = tid; i < DC * 64; i += 256) {
            int c  = i >> 6;
            int nn = i & 63;
            QsT[nn][c] = q[(long long)c * HW + n0 + nn];
            KsT[nn][c] = k[(long long)c * HW + n0 + nn];
        }
        __syncthreads();
        #pragma unroll 8
        for (int kk = 0; kk < 64; kk++) {
            float ra[3], rb[3];
            #pragma unroll
            for (int i = 0; i < 3; i++) ra[i] = QsT[kk][tm * 3 + i];
            #pragma unroll
            for (int j = 0; j < 3; j++) rb[j] = KsT[kk][tn * 3 + j];
            #pragma unroll
            for (int i = 0; i < 3; i++)
                #pragma unroll
                for (int j = 0; j < 3; j++)
                    acc[i][j] = fmaf(ra[i], rb[j], acc[i][j]);
        }
        if (tid < 2 * DC) {
            const int r = (tid < DC) ? tid : tid - DC;
            #pragma unroll 8
            for (int nn = 0; nn < 64; nn++) {
                float v = (tid < DC) ? QsT[nn][r] : KsT[nn][r];
                ssq = fmaf(v, v, ssq);
            }
        }
        __syncthreads();
    }

    float* Sout = Sp + ((long long)chunk * (B * HD) + bh) * (DC * DC);
    #pragma unroll
    for (int i = 0; i < 3; i++)
        #pragma unroll
        for (int j = 0; j < 3; j++)
            Sout[(tm * 3 + i) * DC + tn * 3 + j] = acc[i][j];

    if (tid < 2 * DC)
        ssp[((long long)chunk * (B * HD) + bh) * (2 * DC) + tid] = ssq;
}

// ---------------------------------------------------------------------------
// Reduce partials, apply norms + temperature, softmax. 128 blocks, 256 thr.
// ---------------------------------------------------------------------------
__global__ __launch_bounds__(256) void softmax_kernel(
    const float* __restrict__ Sp, const float* __restrict__ ssp,
    const float* __restrict__ temperature, float* __restrict__ Sout)
{
    const int bh = blockIdx.x;
    const int h  = bh & 7;
    const int tid = threadIdx.x;

    __shared__ float S[DC][DC + 1];
    __shared__ float invq[DC], invk[DC];

    for (int i = tid; i < DC * DC; i += 256) {
        float s = 0.f;
        #pragma unroll
        for (int ch = 0; ch < NCHUNK_QK; ch++)
            s += Sp[((long long)ch * (B * HD) + bh) * (DC * DC) + i];
        S[i / DC][i % DC] = s;
    }
    if (tid < 2 * DC) {
        float s = 0.f;
        #pragma unroll
        for (int ch = 0; ch < NCHUNK_QK; ch++)
            s += ssp[((long long)ch * (B * HD) + bh) * (2 * DC) + tid];
        float inv = 1.0f / fmaxf(sqrtf(s), 1e-12f);
        if (tid < DC) invq[tid] = inv; else invk[tid - DC] = inv;
    }
    __syncthreads();

    if (tid < DC) {
        const float t = temperature[h];
        const float iq = invq[tid] * t;
        float m = -INFINITY;
        float row[DC];
        #pragma unroll 8
        for (int d = 0; d < DC; d++) {
            float v = S[tid][d] * iq * invk[d];
            row[d] = v;
            m = fmaxf(m, v);
        }
        float sum = 0.f;
        #pragma unroll 8
        for (int d = 0; d < DC; d++) {
            float e = expf(row[d] - m);
            row[d] = e;
            sum += e;
        }
        float inv = 1.0f / sum;
        #pragma unroll 8
        for (int d = 0; d < DC; d++)
            Sout[(long long)bh * (DC * DC) + tid * DC + d] = row[d] * inv;
    }
}

// ---------------------------------------------------------------------------
// O = S * V, spatial-split. Writes hi/lo bf16 (pre-split for GEMM3).
// grid = (NCHUNK_SV, B*HD), 256 threads.
// ---------------------------------------------------------------------------
__global__ __launch_bounds__(256) void sv_kernel(
    const float* __restrict__ Sg, const float* __restrict__ kvbuf,
    __nv_bfloat16* __restrict__ oh, __nv_bfloat16* __restrict__ ol)
{
    const int chunk = blockIdx.x;
    const int bh = blockIdx.y;
    const int b  = bh >> 3;
    const int h  = bh & 7;
    const float* v = kvbuf + ((long long)b * KVC + C + h * DC) * HW;
    const long long obase = ((long long)b * C + h * DC) * HW;
    const int nbase = chunk * (HW / NCHUNK_SV);

    __shared__ float S[DC][DC + 1];
    __shared__ float Vs[DC][68];

    const int tid = threadIdx.x;
    const int tm = tid >> 4;
    const int tn = tid & 15;
    const int tn4 = tn * 4;

    for (int i = tid; i < DC * DC; i += 256)
        S[i / DC][i % DC] = Sg[(long long)bh * (DC * DC) + i];
    __syncthreads();

    for (int t = 0; t < (HW / NCHUNK_SV); t += 64) {
        const int n0 = nbase + t;
        for (int i = tid; i < DC * 64; i += 256) {
            int d  = i >> 6;
            int nn = i & 63;
            Vs[d][nn] = v[(long long)d * HW + n0 + nn];
        }
        __syncthreads();
        float acc2[3][4] = {};
        #pragma unroll 4
        for (int d = 0; d < DC; d++) {
            float rs[3];
            #pragma unroll
            for (int i = 0; i < 3; i++) rs[i] = S[tm * 3 + i][d];
            float4 rv = *(const float4*)&Vs[d][tn4];
            #pragma unroll
            for (int i = 0; i < 3; i++) {
                acc2[i][0] = fmaf(rs[i], rv.x, acc2[i][0]);
                acc2[i][1] = fmaf(rs[i], rv.y, acc2[i][1]);
                acc2[i][2] = fmaf(rs[i], rv.z, acc2[i][2]);
                acc2[i][3] = fmaf(rs[i], rv.w, acc2[i][3]);
            }
        }
        #pragma unroll
        for (int i = 0; i < 3; i++) {
            long long off = obase + (long long)(tm * 3 + i) * HW + n0 + tn4;
            uint32_t h0, l0, h1, l1;
            split_pack(acc2[i][0], acc2[i][1], h0, l0);
            split_pack(acc2[i][2], acc2[i][3], h1, l1);
            *(uint2*)&oh[off] = make_uint2(h0, h1);
            *(uint2*)&ol[off] = make_uint2(l0, l1);
        }
        __syncthreads();
    }
}

// ---------------------------------------------------------------------------
// Launch
// ---------------------------------------------------------------------------
extern "C" void kernel_launch(void* const* d_in, const int* in_sizes, int n_in,
                              void* d_out, int out_size)
{
    const float* x           = (const float*)d_in[0];
    const float* query       = (const float*)d_in[1];
    const float* w_kv        = (const float*)d_in[2];
    const float* w_q         = (const float*)d_in[3];
    const float* w_proj      = (const float*)d_in[4];
    const float* temperature = (const float*)d_in[5];
    float* out = (float*)d_out;

    float *kv, *qb, *Sp, *ssp, *S;
    cudaGetSymbolAddress((void**)&kv,  g_kv);
    cudaGetSymbolAddress((void**)&qb,  g_q);
    cudaGetSymbolAddress((void**)&Sp,  g_Sp);
    cudaGetSymbolAddress((void**)&ssp, g_ssp);
    cudaGetSymbolAddress((void**)&S,   g_S);

    __nv_bfloat16 *wkvh, *wkvl, *wqh, *wql, *wph, *wpl, *xh, *xl, *qrh, *qrl, *oh, *ol;
    cudaGetSymbolAddress((void**)&wkvh, g_wkvh);
    cudaGetSymbolAddress((void**)&wkvl, g_wkvl);
    cudaGetSymbolAddress((void**)&wqh,  g_wqh);
    cudaGetSymbolAddress((void**)&wql,  g_wql);
    cudaGetSymbolAddress((void**)&wph,  g_wph);
    cudaGetSymbolAddress((void**)&wpl,  g_wpl);
    cudaGetSymbolAddress((void**)&xh,   g_xh);
    cudaGetSymbolAddress((void**)&xl,   g_xl);
    cudaGetSymbolAddress((void**)&qrh,  g_qrh);
    cudaGetSymbolAddress((void**)&qrl,  g_qrl);
    cudaGetSymbolAddress((void**)&oh,   g_oh);
    cudaGetSymbolAddress((void**)&ol,   g_ol);

    // enable large dynamic smem for the double-buffered GEMMs (idempotent)
    cudaFuncSetAttribute(gemm_db_kernel<C>,
                         cudaFuncAttributeMaxDynamicSharedMemorySize, SMEM_BYTES);
    cudaFuncSetAttribute(gemm_db_kernel<QC>,
                         cudaFuncAttributeMaxDynamicSharedMemorySize, SMEM_BYTES);

    // 0) pre-split all GEMM inputs into bf16 hi/lo
    {
        int n4;
        n4 = KVC * C / 4;
        split_kernel<<<(n4 + 255) / 256, 256>>>(w_kv, wkvh, wkvl, n4);
        n4 = C * QC / 4;
        split_kernel<<<(n4 + 255) / 256, 256>>>(w_q, wqh, wql, n4);
        n4 = C * C / 4;
        split_kernel<<<(n4 + 255) / 256, 256>>>(w_proj, wph, wpl, n4);
        n4 = (int)((long long)B * C * HW / 4);
        split_kernel<<<(n4 + 255) / 256, 256>>>(x, xh, xl, n4);
        n4 = (int)((long long)B * QC * HW / 4);
        split_kernel<<<(n4 + 255) / 256, 256>>>(query, qrh, qrl, n4);
    }

    // 1) kv = w_kv @ x        [768 x 384] x [384 x 4096] per batch
    gemm_db_kernel<C><<<dim3(HW / 128, KVC / 128, B), 256, SMEM_BYTES>>>(
        wkvh, wkvl, xh, xl, kv, KVC);

    // 2) q = w_q @ query      [384 x 192] x [192 x 4096] per batch
    gemm_db_kernel<QC><<<dim3(HW / 128, C / 128, B), 256, SMEM_BYTES>>>(
        wqh, wql, qrh, qrl, qb, C);

    // 3) QK^T partials + sumsq partials
    qk_partial_kernel<<<dim3(NCHUNK_QK, B * HD), 256>>>(qb, kv, Sp, ssp);

    // 4) reduce + norm-scale + softmax
    softmax_kernel<<<B * HD, 256>>>(Sp, ssp, temperature, S);

    // 5) O = S * V (writes pre-split hi/lo)
    sv_kernel<<<dim3(NCHUNK_SV, B * HD), 256>>>(S, kv, oh, ol);

    // 6) out = w_proj @ o     [384 x 384] x [384 x 4096] per batch
    gemm_db_kernel<C><<<dim3(HW / 128, C / 128, B), 256, SMEM_BYTES>>>(
        wph, wpl, oh, ol, out, C);
}

// round 10
// speedup vs baseline: 1.2460x; 1.0981x over previous
#include <cuda_runtime.h>
#include <cuda_bf16.h>
#include <math.h>
#include <stdint.h>

// Problem constants
#define B   16
#define C   384
#define HD  8
#define DC  48
#define HW  4096
#define QC  192
#define KVC 768

#define NCHUNK_QK 8
#define NCHUNK_SV 16

// Scratch (device globals)
__device__ float g_Sp [NCHUNK_QK * B * HD * DC * DC];
__device__ float g_ssp[NCHUNK_QK * B * HD * 2 * DC];

// bf16 hi/lo operand buffers
__device__ __nv_bfloat16 g_wkvh[KVC * C],  g_wkvl[KVC * C];
__device__ __nv_bfloat16 g_wqh [C * QC],   g_wql [C * QC];
__device__ __nv_bfloat16 g_wph [C * C],    g_wpl [C * C];
__device__ __nv_bfloat16 g_xh [(long long)B * C  * HW], g_xl [(long long)B * C  * HW];
__device__ __nv_bfloat16 g_qrh[(long long)B * QC * HW], g_qrl[(long long)B * QC * HW];
__device__ __nv_bfloat16 g_kvh[(long long)B * KVC * HW], g_kvl[(long long)B * KVC * HW];
__device__ __nv_bfloat16 g_qh [(long long)B * C  * HW], g_ql [(long long)B * C  * HW];
__device__ __nv_bfloat16 g_oh [(long long)B * C  * HW], g_ol [(long long)B * C  * HW];
__device__ __nv_bfloat16 g_Sh [B * HD * DC * DC], g_Sl [B * HD * DC * DC];

// ---------------------------------------------------------------------------
// PTX helpers
// ---------------------------------------------------------------------------
__device__ __forceinline__ uint32_t smem_u32(const void* p) {
    uint32_t a;
    asm("{ .reg .u64 t; cvta.to.shared.u64 t, %1; cvt.u32.u64 %0, t; }" : "=r"(a) : "l"(p));
    return a;
}
__device__ __forceinline__ void cp16(uint32_t dst, const void* src) {
    asm volatile("cp.async.ca.shared.global [%0], [%1], 16;" :: "r"(dst), "l"(src));
}
#define CP_COMMIT() asm volatile("cp.async.commit_group;" ::: "memory")
#define CP_WAIT0()  asm volatile("cp.async.wait_group 0;" ::: "memory")
#define CP_WAIT1()  asm volatile("cp.async.wait_group 1;" ::: "memory")

__device__ __forceinline__ void ldsm_x4(uint32_t r[4], uint32_t addr) {
    asm volatile("ldmatrix.sync.aligned.m8n8.x4.shared.b16 {%0,%1,%2,%3}, [%4];"
                 : "=r"(r[0]), "=r"(r[1]), "=r"(r[2]), "=r"(r[3]) : "r"(addr));
}
__device__ __forceinline__ void ldsm_x4_t(uint32_t r[4], uint32_t addr) {
    asm volatile("ldmatrix.sync.aligned.m8n8.x4.trans.shared.b16 {%0,%1,%2,%3}, [%4];"
                 : "=r"(r[0]), "=r"(r[1]), "=r"(r[2]), "=r"(r[3]) : "r"(addr));
}
__device__ __forceinline__ void mma_bf16(float* c, const uint32_t a[4],
                                         uint32_t b0, uint32_t b1) {
    asm volatile(
        "mma.sync.aligned.m16n8k16.row.col.f32.bf16.bf16.f32 "
        "{%0,%1,%2,%3}, {%4,%5,%6,%7}, {%8,%9}, {%0,%1,%2,%3};"
        : "+f"(c[0]), "+f"(c[1]), "+f"(c[2]), "+f"(c[3])
        : "r"(a[0]), "r"(a[1]), "r"(a[2]), "r"(a[3]), "r"(b0), "r"(b1));
}

// hi/lo bf16 split: x ~= hi + lo
__device__ __forceinline__ void split_pack(float x0, float x1,
                                           uint32_t& ph, uint32_t& pl) {
    __nv_bfloat16 h0 = __float2bfloat16_rn(x0);
    __nv_bfloat16 h1 = __float2bfloat16_rn(x1);
    __nv_bfloat16 l0 = __float2bfloat16_rn(x0 - __bfloat162float(h0));
    __nv_bfloat16 l1 = __float2bfloat16_rn(x1 - __bfloat162float(h1));
    ph = (uint32_t)__bfloat16_as_ushort(h0) | ((uint32_t)__bfloat16_as_ushort(h1) << 16);
    pl = (uint32_t)__bfloat16_as_ushort(l0) | ((uint32_t)__bfloat16_as_ushort(l1) << 16);
}
__device__ __forceinline__ float rec2(uint32_t ph, uint32_t pl, int half) {
    uint16_t h = half ? (uint16_t)(ph >> 16) : (uint16_t)ph;
    uint16_t l = half ? (uint16_t)(pl >> 16) : (uint16_t)pl;
    return __bfloat162float(__ushort_as_bfloat16(h)) +
           __bfloat162float(__ushort_as_bfloat16(l));
}

// ---------------------------------------------------------------------------
// fp32 -> bf16 hi/lo pre-split (weights, x, query)
// ---------------------------------------------------------------------------
__global__ __launch_bounds__(256) void split_kernel(
    const float* __restrict__ src, __nv_bfloat16* __restrict__ dh,
    __nv_bfloat16* __restrict__ dl, int n4)
{
    int i = blockIdx.x * 256 + threadIdx.x;
    if (i < n4) {
        float4 v = ((const float4*)src)[i];
        uint32_t h0, l0, h1, l1;
        split_pack(v.x, v.y, h0, l0);
        split_pack(v.z, v.w, h1, l1);
        ((uint2*)dh)[i] = make_uint2(h0, h1);
        ((uint2*)dl)[i] = make_uint2(l0, l1);
    }
}

// ---------------------------------------------------------------------------
// Double-buffered bf16-split tensor-core GEMM on pre-split operands.
// SPLIT_OUT: epilogue writes bf16 hi/lo (Oh/Ol) instead of fp32 (Of).
// ---------------------------------------------------------------------------
#define WPITCH 40
#define APITCH 136
#define WTE (128 * WPITCH)
#define ATE (32 * APITCH)
#define BUFE (2 * WTE + 2 * ATE)
#define SMEM_BYTES (2 * BUFE * 2)

template<int K, bool SPLIT_OUT>
__global__ __launch_bounds__(256, 2) void gemm_db_kernel(
    const __nv_bfloat16* __restrict__ Wh, const __nv_bfloat16* __restrict__ Wl,
    const __nv_bfloat16* __restrict__ Ah, const __nv_bfloat16* __restrict__ Al,
    float* __restrict__ Of,
    __nv_bfloat16* __restrict__ Oh, __nv_bfloat16* __restrict__ Ol,
    int OCtot)
{
    extern __shared__ __align__(16) uint16_t dynsmem[];
    const uint32_t uS = smem_u32(dynsmem);

    const int tid  = threadIdx.x;
    const int warp = tid >> 5;
    const int lane = tid & 31;
    const int s0 = blockIdx.x * 128;
    const int j0 = blockIdx.y * 128;
    const int b  = blockIdx.z;

    const __nv_bfloat16* Aph = Ah + (long long)b * K * HW;
    const __nv_bfloat16* Apl = Al + (long long)b * K * HW;
    const long long obase = ((long long)b * OCtot + j0) * HW + s0;

    const int mbase = (warp >> 1) * 32;
    const int nbase = (warp & 1) * 64;

    float acc[64];
    #pragma unroll
    for (int i = 0; i < 64; i++) acc[i] = 0.f;

    const int lrow  = (lane & 7) + ((lane >> 3) & 1) * 8;
    const int lhalf = lane >> 4;

    const int wj = tid >> 2, wq = tid & 3;
    const int ak = tid >> 4, ag = tid & 15;

    auto stage = [&](int kc, int buf) {
        const uint32_t bWh = uS + (uint32_t)(buf * BUFE) * 2;
        const uint32_t bWl = bWh + WTE * 2;
        const uint32_t bAh = bWl + WTE * 2;
        const uint32_t bAl = bAh + ATE * 2;
        const int k0 = kc * 32;
        #pragma unroll
        for (int i = 0; i < 2; i++) {
            int j = wj + i * 64;
            uint32_t d = (uint32_t)(j * WPITCH + wq * 8) * 2;
            long long g = (long long)(j0 + j) * K + k0 + wq * 8;
            cp16(bWh + d, Wh + g);
            cp16(bWl + d, Wl + g);
        }
        #pragma unroll
        for (int i = 0; i < 2; i++) {
            int kk = ak + i * 16;
            uint32_t d = (uint32_t)(kk * APITCH + ag * 8) * 2;
            long long g = (long long)(k0 + kk) * HW + s0 + ag * 8;
            cp16(bAh + d, Aph + g);
            cp16(bAl + d, Apl + g);
        }
        CP_COMMIT();
    };

    const int NK = K / 32;
    stage(0, 0);

    for (int kc = 0; kc < NK; kc++) {
        const int buf = kc & 1;
        if (kc + 1 < NK) {
            stage(kc + 1, (kc + 1) & 1);
            CP_WAIT1();
        } else {
            CP_WAIT0();
        }
        __syncthreads();

        const uint32_t bWh = uS + (uint32_t)(buf * BUFE) * 2;
        const uint32_t bWl = bWh + WTE * 2;
        const uint32_t bAh = bWl + WTE * 2;
        const uint32_t bAl = bAh + ATE * 2;

        #pragma unroll
        for (int kh = 0; kh < 2; kh++) {
            uint32_t ah[2][4], al[2][4];
            #pragma unroll
            for (int mt = 0; mt < 2; mt++) {
                uint32_t off = (uint32_t)((mbase + mt * 16 + lrow) * (WPITCH * 2)
                                          + kh * 32 + lhalf * 16);
                ldsm_x4(ah[mt], bWh + off);
                ldsm_x4(al[mt], bWl + off);
            }
            #pragma unroll
            for (int np = 0; np < 4; np++) {
                uint32_t boff = (uint32_t)((kh * 16 + lrow) * (APITCH * 2)
                                           + (nbase + np * 16 + lhalf * 8) * 2);
                uint32_t bh[4], bl[4];
                ldsm_x4_t(bh, bAh + boff);
                ldsm_x4_t(bl, bAl + boff);
                #pragma unroll
                for (int nt2 = 0; nt2 < 2; nt2++) {
                    const uint32_t bh0 = bh[nt2 * 2], bh1 = bh[nt2 * 2 + 1];
                    const uint32_t bl0 = bl[nt2 * 2], bl1 = bl[nt2 * 2 + 1];
                    const int nt = np * 2 + nt2;
                    #pragma unroll
                    for (int mt = 0; mt < 2; mt++) {
                        float* cp = acc + (mt * 8 + nt) * 4;
                        mma_bf16(cp, ah[mt], bh0, bh1);
                        mma_bf16(cp, ah[mt], bl0, bl1);
                        mma_bf16(cp, al[mt], bh0, bh1);
                    }
                }
            }
        }
        __syncthreads();
    }

    // ---- epilogue ----
    const int crow = lane >> 2;
    const int ccol = (lane & 3) * 2;
    #pragma unroll
    for (int mt = 0; mt < 2; mt++) {
        #pragma unroll
        for (int nt = 0; nt < 8; nt++) {
            const float* cp = acc + (mt * 8 + nt) * 4;
            long long r0 = obase + (long long)(mbase + mt * 16 + crow) * HW
                         + nbase + nt * 8 + ccol;
            long long r1 = r0 + 8 * HW;
            if (SPLIT_OUT) {
                uint32_t h0, l0, h1, l1;
                split_pack(cp[0], cp[1], h0, l0);
                split_pack(cp[2], cp[3], h1, l1);
                *(uint32_t*)&Oh[r0] = h0;  *(uint32_t*)&Ol[r0] = l0;
                *(uint32_t*)&Oh[r1] = h1;  *(uint32_t*)&Ol[r1] = l1;
            } else {
                *(float2*)&Of[r0] = make_float2(cp[0], cp[1]);
                *(float2*)&Of[r1] = make_float2(cp[2], cp[3]);
            }
        }
    }
}

// ---------------------------------------------------------------------------
// qk_mma: S_partial = Q K^T over a 512-spatial slice (bf16-split 3-term MMA)
// + per-row sumsq partials. grid = (NCHUNK_QK, B*HD), 256 threads.
// Q,K tiles staged [48 ch][128 s] hi/lo; both operands K-major -> non-trans ldsm.
// warp w handles k16-step w of each 128-slice; computes full 48x48 partial.
// ---------------------------------------------------------------------------
#define QKP 136                       // tile pitch (bf16 elems)
#define QK_ARR (48 * QKP)             // per-array elems
#define QK_SMEM (4 * QK_ARR * 2)      // 52224 bytes (dynamic)

__global__ __launch_bounds__(256) void qk_mma_kernel(
    const __nv_bfloat16* __restrict__ qh, const __nv_bfloat16* __restrict__ ql,
    const __nv_bfloat16* __restrict__ kh, const __nv_bfloat16* __restrict__ kl,
    float* __restrict__ Sp, float* __restrict__ ssp)
{
    extern __shared__ __align__(16) uint16_t dynsmem[];
    __shared__ float Sred[DC][DC + 1];

    const uint32_t uQh = smem_u32(dynsmem);
    const uint32_t uQl = uQh + QK_ARR * 2;
    const uint32_t uKh = uQl + QK_ARR * 2;
    const uint32_t uKl = uKh + QK_ARR * 2;

    const int chunk = blockIdx.x;
    const int bh = blockIdx.y;
    const int b  = bh >> 3;
    const int h  = bh & 7;
    const long long qbase = ((long long)b * C   + h * DC) * HW;
    const long long kbase = ((long long)b * KVC + h * DC) * HW;
    const int sbase = chunk * (HW / NCHUNK_QK);

    const int tid  = threadIdx.x;
    const int warp = tid >> 5;
    const int lane = tid & 31;
    const int lrow  = (lane & 7) + ((lane >> 3) & 1) * 8;
    const int lhalf = lane >> 4;
    // B-operand lane mapping (non-trans from [n][k] layout)
    const int brow = ((lane >> 4) << 3) + (lane & 7);
    const int bcol = ((lane >> 3) & 1) * 8;

    const int kcol = warp * 16;   // this warp's k16-step within the 128 slice

    float acc[72];
    #pragma unroll
    for (int i = 0; i < 72; i++) acc[i] = 0.f;
    float ssq = 0.f;

    for (int it = 0; it < 4; it++) {
        const int s0 = sbase + it * 128;
        // stage 4 tiles (48 x 128 bf16 each): 3072 cp16 over 256 threads
        #pragma unroll
        for (int i = 0; i < 3; i++) {
            int idx = i * 256 + tid;       // 0..767
            int row = idx >> 4, g = idx & 15;
            uint32_t d = (uint32_t)(row * QKP + g * 8) * 2;
            long long gq = qbase + (long long)row * HW + s0 + g * 8;
            long long gk = kbase + (long long)row * HW + s0 + g * 8;
            cp16(uQh + d, qh + gq);
            cp16(uQl + d, ql + gq);
            cp16(uKh + d, kh + gk);
            cp16(uKl + d, kl + gk);
        }
        CP_COMMIT();
        CP_WAIT0();
        __syncthreads();

        // B frags (K): 6 n8 tiles, hi & lo
        uint32_t bhf[12], blf[12];
        #pragma unroll
        for (int g = 0; g < 3; g++) {
            uint32_t off = (uint32_t)((g * 16 + brow) * QKP + kcol + bcol) * 2;
            ldsm_x4(&bhf[g * 4], uKh + off);
            ldsm_x4(&blf[g * 4], uKl + off);
        }
        #pragma unroll
        for (int mt = 0; mt < 3; mt++) {
            uint32_t ah[4], al[4];
            uint32_t off = (uint32_t)((mt * 16 + lrow) * QKP + kcol + lhalf * 8) * 2;
            ldsm_x4(ah, uQh + off);
            ldsm_x4(al, uQl + off);
            #pragma unroll
            for (int n8 = 0; n8 < 6; n8++) {
                float* cp = acc + (mt * 6 + n8) * 4;
                const uint32_t b0h = bhf[n8 * 2], b1h = bhf[n8 * 2 + 1];
                mma_bf16(cp, ah, b0h, b1h);
                mma_bf16(cp, ah, blf[n8 * 2], blf[n8 * 2 + 1]);
                mma_bf16(cp, al, b0h, b1h);
            }
        }

        // sumsq partials from the staged tiles (threads 0..95)
        if (tid < 2 * DC) {
            const int r = (tid < DC) ? tid : tid - DC;
            const uint16_t* ph = (const uint16_t*)dynsmem
                               + (tid < DC ? 0 : 2 * QK_ARR) + r * QKP;
            const uint16_t* pl = ph + QK_ARR;
            #pragma unroll 8
            for (int g = 0; g < 64; g++) {
                uint32_t vh = *(const uint32_t*)(ph + g * 2);
                uint32_t vl = *(const uint32_t*)(pl + g * 2);
                float a = rec2(vh, vl, 0);
                float c = rec2(vh, vl, 1);
                ssq = fmaf(a, a, ssq);
                ssq = fmaf(c, c, ssq);
            }
        }
        __syncthreads();
    }

    // block-reduce the 8 warp partials
    for (int i = tid; i < DC * DC; i += 256) Sred[i / DC][i % DC] = 0.f;
    __syncthreads();
    const int crow = lane >> 2;
    const int ccol = (lane & 3) * 2;
    #pragma unroll
    for (int mt = 0; mt < 3; mt++) {
        #pragma unroll
        for (int n8 = 0; n8 < 6; n8++) {
            const float* cp = acc + (mt * 6 + n8) * 4;
            int r0 = mt * 16 + crow, c0 = n8 * 8 + ccol;
            atomicAdd(&Sred[r0][c0],     cp[0]);
            atomicAdd(&Sred[r0][c0 + 1], cp[1]);
            atomicAdd(&Sred[r0 + 8][c0],     cp[2]);
            atomicAdd(&Sred[r0 + 8][c0 + 1], cp[3]);
        }
    }
    __syncthreads();

    float* Sout = Sp + ((long long)chunk * (B * HD) + bh) * (DC * DC);
    for (int i = tid; i < DC * DC; i += 256)
        Sout[i] = Sred[i / DC][i % DC];
    if (tid < 2 * DC)
        ssp[((long long)chunk * (B * HD) + bh) * (2 * DC) + tid] = ssq;
}

// ---------------------------------------------------------------------------
// Reduce partials, apply norms + temperature, softmax; write S as bf16 hi/lo.
// ---------------------------------------------------------------------------
__global__ __launch_bounds__(256) void softmax_kernel(
    const float* __restrict__ Sp, const float* __restrict__ ssp,
    const float* __restrict__ temperature,
    __nv_bfloat16* __restrict__ ShG, __nv_bfloat16* __restrict__ SlG)
{
    const int bh = blockIdx.x;
    const int h  = bh & 7;
    const int tid = threadIdx.x;

    __shared__ float S[DC][DC + 1];
    __shared__ float invq[DC], invk[DC];

    for (int i = tid; i < DC * DC; i += 256) {
        float s = 0.f;
        #pragma unroll
        for (int ch = 0; ch < NCHUNK_QK; ch++)
            s += Sp[((long long)ch * (B * HD) + bh) * (DC * DC) + i];
        S[i / DC][i % DC] = s;
    }
    if (tid < 2 * DC) {
        float s = 0.f;
        #pragma unroll
        for (int ch = 0; ch < NCHUNK_QK; ch++)
            s += ssp[((long long)ch * (B * HD) + bh) * (2 * DC) + tid];
        float inv = 1.0f / fmaxf(sqrtf(s), 1e-12f);
        if (tid < DC) invq[tid] = inv; else invk[tid - DC] = inv;
    }
    __syncthreads();

    if (tid < DC) {
        const float t = temperature[h];
        const float iq = invq[tid] * t;
        float m = -INFINITY;
        float row[DC];
        #pragma unroll 8
        for (int d = 0; d < DC; d++) {
            float v = S[tid][d] * iq * invk[d];
            row[d] = v;
            m = fmaxf(m, v);
        }
        float sum = 0.f;
        #pragma unroll 8
        for (int d = 0; d < DC; d++) {
            float e = expf(row[d] - m);
            row[d] = e;
            sum += e;
        }
        float inv = 1.0f / sum;
        uint32_t* oh = (uint32_t*)(ShG + (long long)bh * (DC * DC) + tid * DC);
        uint32_t* ol = (uint32_t*)(SlG + (long long)bh * (DC * DC) + tid * DC);
        #pragma unroll
        for (int d = 0; d < DC; d += 2) {
            uint32_t ph, pl;
            split_pack(row[d] * inv, row[d + 1] * inv, ph, pl);
            oh[d / 2] = ph;
            ol[d / 2] = pl;
        }
    }
}

// ---------------------------------------------------------------------------
// sv_mma: O = S * V via bf16-split MMA (K=48). grid = (NCHUNK_SV, B*HD).
// A = S hi/lo [48x48] row-major (non-trans ldsm), B = V [d][s] (trans ldsm).
// Output written as bf16 hi/lo for GEMM3.
// ---------------------------------------------------------------------------
#define SPITCH 56
#define VPITCH 136

__global__ __launch_bounds__(256) void sv_mma_kernel(
    const __nv_bfloat16* __restrict__ ShG, const __nv_bfloat16* __restrict__ SlG,
    const __nv_bfloat16* __restrict__ vh, const __nv_bfloat16* __restrict__ vl,
    __nv_bfloat16* __restrict__ oh, __nv_bfloat16* __restrict__ ol)
{
    __shared__ __align__(16) uint16_t sSh[DC * SPITCH];
    __shared__ __align__(16) uint16_t sSl[DC * SPITCH];
    __shared__ __align__(16) uint16_t sVh[DC * VPITCH];
    __shared__ __align__(16) uint16_t sVl[DC * VPITCH];

    const int chunk = blockIdx.x;
    const int bh = blockIdx.y;
    const int b  = bh >> 3;
    const int h  = bh & 7;
    const long long vbase = ((long long)b * KVC + C + h * DC) * HW;
    const long long obase = ((long long)b * C + h * DC) * HW;
    const int sbase = chunk * (HW / NCHUNK_SV);

    const int tid  = threadIdx.x;
    const int warp = tid >> 5;
    const int lane = tid & 31;
    const int lrow  = (lane & 7) + ((lane >> 3) & 1) * 8;
    const int lhalf = lane >> 4;
    const int crow = lane >> 2;
    const int ccol = (lane & 3) * 2;

    const uint32_t uSh = smem_u32(sSh);
    const uint32_t uSl = smem_u32(sSl);
    const uint32_t uVh = smem_u32(sVh);
    const uint32_t uVl = smem_u32(sVl);

    // stage S (48x48 hi/lo): 288 cp16 per array
    for (int idx = tid; idx < 288; idx += 256) {
        int row = idx / 6, g = idx % 6;
        uint32_t d = (uint32_t)(row * SPITCH + g * 8) * 2;
        long long s = (long long)bh * (DC * DC) + row * DC + g * 8;
        cp16(uSh + d, ShG + s);
        cp16(uSl + d, SlG + s);
    }

    const int n0w = warp * 16;

    for (int it = 0; it < 2; it++) {
        const int s0 = sbase + it * 128;
        // stage V tile (48 x 128 hi/lo)
        #pragma unroll
        for (int i = 0; i < 3; i++) {
            int idx = i * 256 + tid;      // 0..767
            int row = idx >> 4, g = idx & 15;
            uint32_t d = (uint32_t)(row * VPITCH + g * 8) * 2;
            long long gsrc = vbase + (long long)row * HW + s0 + g * 8;
            cp16(uVh + d, vh + gsrc);
            cp16(uVl + d, vl + gsrc);
        }
        CP_COMMIT();
        CP_WAIT0();
        __syncthreads();

        float acc[24];
        #pragma unroll
        for (int i = 0; i < 24; i++) acc[i] = 0.f;

        #pragma unroll
        for (int ks = 0; ks < 3; ks++) {
            uint32_t bhf[4], blf[4];
            uint32_t boff = (uint32_t)((ks * 16 + lrow) * VPITCH
                                       + n0w + lhalf * 8) * 2;
            ldsm_x4_t(bhf, uVh + boff);
            ldsm_x4_t(blf, uVl + boff);
            #pragma unroll
            for (int mt = 0; mt < 3; mt++) {
                uint32_t ah[4], al[4];
                uint32_t aoff = (uint32_t)((mt * 16 + lrow) * SPITCH
                                           + ks * 16 + lhalf * 8) * 2;
                ldsm_x4(ah, uSh + aoff);
                ldsm_x4(al, uSl + aoff);
                #pragma unroll
                for (int nt2 = 0; nt2 < 2; nt2++) {
                    float* cp = acc + (mt * 2 + nt2) * 4;
                    const uint32_t b0 = bhf[nt2 * 2], b1 = bhf[nt2 * 2 + 1];
                    mma_bf16(cp, ah, b0, b1);
                    mma_bf16(cp, ah, blf[nt2 * 2], blf[nt2 * 2 + 1]);
                    mma_bf16(cp, al, b0, b1);
                }
            }
        }

        // epilogue: split and store
        #pragma unroll
        for (int mt = 0; mt < 3; mt++) {
            #pragma unroll
            for (int nt2 = 0; nt2 < 2; nt2++) {
                const float* cp = acc + (mt * 2 + nt2) * 4;
                int cc = mt * 16 + crow;
                int ss = s0 + n0w + nt2 * 8 + ccol;
                long long r0 = obase + (long long)cc * HW + ss;
                long long r1 = r0 + 8 * HW;
                uint32_t h0, l0, h1, l1;
                split_pack(cp[0], cp[1], h0, l0);
                split_pack(cp[2], cp[3], h1, l1);
                *(uint32_t*)&oh[r0] = h0;  *(uint32_t*)&ol[r0] = l0;
                *(uint32_t*)&oh[r1] = h1;  *(uint32_t*)&ol[r1] = l1;
            }
        }
        __syncthreads();
    }
}

// ---------------------------------------------------------------------------
// Launch
// ---------------------------------------------------------------------------
extern "C" void kernel_launch(void* const* d_in, const int* in_sizes, int n_in,
                              void* d_out, int out_size)
{
    const float* x           = (const float*)d_in[0];
    const float* query       = (const float*)d_in[1];
    const float* w_kv        = (const float*)d_in[2];
    const float* w_q         = (const float*)d_in[3];
    const float* w_proj      = (const float*)d_in[4];
    const float* temperature = (const float*)d_in[5];
    float* out = (float*)d_out;

    float *Sp, *ssp;
    cudaGetSymbolAddress((void**)&Sp,  g_Sp);
    cudaGetSymbolAddress((void**)&ssp, g_ssp);

    __nv_bfloat16 *wkvh, *wkvl, *wqh, *wql, *wph, *wpl, *xh, *xl, *qrh, *qrl;
    __nv_bfloat16 *kvh, *kvl, *qh, *ql, *oh, *ol, *Sh, *Sl;
    cudaGetSymbolAddress((void**)&wkvh, g_wkvh);
    cudaGetSymbolAddress((void**)&wkvl, g_wkvl);
    cudaGetSymbolAddress((void**)&wqh,  g_wqh);
    cudaGetSymbolAddress((void**)&wql,  g_wql);
    cudaGetSymbolAddress((void**)&wph,  g_wph);
    cudaGetSymbolAddress((void**)&wpl,  g_wpl);
    cudaGetSymbolAddress((void**)&xh,   g_xh);
    cudaGetSymbolAddress((void**)&xl,   g_xl);
    cudaGetSymbolAddress((void**)&qrh,  g_qrh);
    cudaGetSymbolAddress((void**)&qrl,  g_qrl);
    cudaGetSymbolAddress((void**)&kvh,  g_kvh);
    cudaGetSymbolAddress((void**)&kvl,  g_kvl);
    cudaGetSymbolAddress((void**)&qh,   g_qh);
    cudaGetSymbolAddress((void**)&ql,   g_ql);
    cudaGetSymbolAddress((void**)&oh,   g_oh);
    cudaGetSymbolAddress((void**)&ol,   g_ol);
    cudaGetSymbolAddress((void**)&Sh,   g_Sh);
    cudaGetSymbolAddress((void**)&Sl,   g_Sl);

    cudaFuncSetAttribute(gemm_db_kernel<C, true>,
                         cudaFuncAttributeMaxDynamicSharedMemorySize, SMEM_BYTES);
    cudaFuncSetAttribute(gemm_db_kernel<QC, true>,
                         cudaFuncAttributeMaxDynamicSharedMemorySize, SMEM_BYTES);
    cudaFuncSetAttribute(gemm_db_kernel<C, false>,
                         cudaFuncAttributeMaxDynamicSharedMemorySize, SMEM_BYTES);
    cudaFuncSetAttribute(qk_mma_kernel,
                         cudaFuncAttributeMaxDynamicSharedMemorySize, QK_SMEM);

    // 0) pre-split inputs
    {
        int n4;
        n4 = KVC * C / 4;
        split_kernel<<<(n4 + 255) / 256, 256>>>(w_kv, wkvh, wkvl, n4);
        n4 = C * QC / 4;
        split_kernel<<<(n4 + 255) / 256, 256>>>(w_q, wqh, wql, n4);
        n4 = C * C / 4;
        split_kernel<<<(n4 + 255) / 256, 256>>>(w_proj, wph, wpl, n4);
        n4 = (int)((long long)B * C * HW / 4);
        split_kernel<<<(n4 + 255) / 256, 256>>>(x, xh, xl, n4);
        n4 = (int)((long long)B * QC * HW / 4);
        split_kernel<<<(n4 + 255) / 256, 256>>>(query, qrh, qrl, n4);
    }

    // 1) kv = w_kv @ x  -> bf16 hi/lo
    gemm_db_kernel<C, true><<<dim3(HW / 128, KVC / 128, B), 256, SMEM_BYTES>>>(
        wkvh, wkvl, xh, xl, nullptr, kvh, kvl, KVC);

    // 2) q = w_q @ query -> bf16 hi/lo
    gemm_db_kernel<QC, true><<<dim3(HW / 128, C / 128, B), 256, SMEM_BYTES>>>(
        wqh, wql, qrh, qrl, nullptr, qh, ql, C);

    // 3) QK^T partials + sumsq (tensor cores)
    qk_mma_kernel<<<dim3(NCHUNK_QK, B * HD), 256, QK_SMEM>>>(
        qh, ql, kvh, kvl, Sp, ssp);

    // 4) reduce + norm-scale + softmax -> S hi/lo
    softmax_kernel<<<B * HD, 256>>>(Sp, ssp, temperature, Sh, Sl);

    // 5) O = S * V (tensor cores) -> bf16 hi/lo
    sv_mma_kernel<<<dim3(NCHUNK_SV, B * HD), 256>>>(Sh, Sl, kvh, kvl, oh, ol);

    // 6) out = w_proj @ o -> fp32
    gemm_db_kernel<C, false><<<dim3(HW / 128, C / 128, B), 256, SMEM_BYTES>>>(
        wph, wpl, oh, ol, out, nullptr, nullptr, C);
}

// round 11
// speedup vs baseline: 1.6054x; 1.2885x over previous
#include <cuda_runtime.h>
#include <cuda_fp16.h>
#include <math.h>
#include <stdint.h>

// Problem constants
#define B   16
#define C   384
#define HD  8
#define DC  48
#define HW  4096
#define QC  192
#define KVC 768

#define NCHUNK_QK 8
#define NCHUNK_SV 16

// Scratch (device globals)
__device__ float g_Sp [NCHUNK_QK * B * HD * DC * DC];
__device__ float g_ssp[NCHUNK_QK * B * HD * 2 * DC];

// fp16 operand buffers
__device__ __half g_wkvh[KVC * C],  g_wkvl[KVC * C];
__device__ __half g_wqh [C * QC],   g_wql [C * QC];
__device__ __half g_wph [C * C],    g_wpl [C * C];
__device__ __half g_xh [(long long)B * C  * HW];             // 1-limb
__device__ __half g_qrh[(long long)B * QC * HW];             // 1-limb
__device__ __half g_kvh[(long long)B * KVC * HW], g_kvl[(long long)B * KVC * HW];
__device__ __half g_qh [(long long)B * C  * HW], g_ql [(long long)B * C  * HW];
__device__ __half g_oh [(long long)B * C  * HW];             // 1-limb
__device__ __half g_Sh [B * HD * DC * DC], g_Sl [B * HD * DC * DC];

// ---------------------------------------------------------------------------
// PTX helpers
// ---------------------------------------------------------------------------
__device__ __forceinline__ uint32_t smem_u32(const void* p) {
    uint32_t a;
    asm("{ .reg .u64 t; cvta.to.shared.u64 t, %1; cvt.u32.u64 %0, t; }" : "=r"(a) : "l"(p));
    return a;
}
__device__ __forceinline__ void cp16(uint32_t dst, const void* src) {
    asm volatile("cp.async.ca.shared.global [%0], [%1], 16;" :: "r"(dst), "l"(src));
}
#define CP_COMMIT() asm volatile("cp.async.commit_group;" ::: "memory")
#define CP_WAIT0()  asm volatile("cp.async.wait_group 0;" ::: "memory")
#define CP_WAIT1()  asm volatile("cp.async.wait_group 1;" ::: "memory")

__device__ __forceinline__ void ldsm_x4(uint32_t r[4], uint32_t addr) {
    asm volatile("ldmatrix.sync.aligned.m8n8.x4.shared.b16 {%0,%1,%2,%3}, [%4];"
                 : "=r"(r[0]), "=r"(r[1]), "=r"(r[2]), "=r"(r[3]) : "r"(addr));
}
__device__ __forceinline__ void ldsm_x4_t(uint32_t r[4], uint32_t addr) {
    asm volatile("ldmatrix.sync.aligned.m8n8.x4.trans.shared.b16 {%0,%1,%2,%3}, [%4];"
                 : "=r"(r[0]), "=r"(r[1]), "=r"(r[2]), "=r"(r[3]) : "r"(addr));
}
__device__ __forceinline__ void mma_f16(float* c, const uint32_t a[4],
                                        uint32_t b0, uint32_t b1) {
    asm volatile(
        "mma.sync.aligned.m16n8k16.row.col.f32.f16.f16.f32 "
        "{%0,%1,%2,%3}, {%4,%5,%6,%7}, {%8,%9}, {%0,%1,%2,%3};"
        : "+f"(c[0]), "+f"(c[1]), "+f"(c[2]), "+f"(c[3])
        : "r"(a[0]), "r"(a[1]), "r"(a[2]), "r"(a[3]), "r"(b0), "r"(b1));
}

// fp16 hi/lo split: x ~= hi + lo (~22 mantissa bits)
__device__ __forceinline__ void split_pack_h(float x0, float x1,
                                             uint32_t& ph, uint32_t& pl) {
    __half h0 = __float2half_rn(x0);
    __half h1 = __float2half_rn(x1);
    __half l0 = __float2half_rn(x0 - __half2float(h0));
    __half l1 = __float2half_rn(x1 - __half2float(h1));
    ph = (uint32_t)__half_as_ushort(h0) | ((uint32_t)__half_as_ushort(h1) << 16);
    pl = (uint32_t)__half_as_ushort(l0) | ((uint32_t)__half_as_ushort(l1) << 16);
}
__device__ __forceinline__ uint32_t pack_h2(float x0, float x1) {
    return (uint32_t)__half_as_ushort(__float2half_rn(x0))
         | ((uint32_t)__half_as_ushort(__float2half_rn(x1)) << 16);
}
__device__ __forceinline__ float rec2h(uint32_t ph, uint32_t pl, int half) {
    uint16_t h = half ? (uint16_t)(ph >> 16) : (uint16_t)ph;
    uint16_t l = half ? (uint16_t)(pl >> 16) : (uint16_t)pl;
    return __half2float(__ushort_as_half(h)) + __half2float(__ushort_as_half(l));
}

// ---------------------------------------------------------------------------
// fp32 -> fp16 hi/lo split (weights)
// ---------------------------------------------------------------------------
__global__ __launch_bounds__(256) void split2_kernel(
    const float* __restrict__ src, __half* __restrict__ dh,
    __half* __restrict__ dl, int n4)
{
    int i = blockIdx.x * 256 + threadIdx.x;
    if (i < n4) {
        float4 v = ((const float4*)src)[i];
        uint32_t h0, l0, h1, l1;
        split_pack_h(v.x, v.y, h0, l0);
        split_pack_h(v.z, v.w, h1, l1);
        ((uint2*)dh)[i] = make_uint2(h0, h1);
        ((uint2*)dl)[i] = make_uint2(l0, l1);
    }
}

// fp32 -> fp16 hi only (activations x, query)
__global__ __launch_bounds__(256) void split1_kernel(
    const float* __restrict__ src, __half* __restrict__ dh, int n4)
{
    int i = blockIdx.x * 256 + threadIdx.x;
    if (i < n4) {
        float4 v = ((const float4*)src)[i];
        ((uint2*)dh)[i] = make_uint2(pack_h2(v.x, v.y), pack_h2(v.z, v.w));
    }
}

// ---------------------------------------------------------------------------
// fp16 2-term tensor-core GEMM: Out[b][j][s] = sum_k W[j][k] * Act[b][k][s]
// W = 2-limb fp16 (Wh,Wl), Act = 1-limb fp16. out = Wh*A + Wl*A.
// CTA tile 128(j) x 128(s), K-chunk 32, 8 warps (4m x 2n), double-buffered.
// ---------------------------------------------------------------------------
#define WPITCH 40
#define APITCH 136
#define WTE (128 * WPITCH)           // 5120
#define ATE (32 * APITCH)            // 4352
#define BUFE (2 * WTE + ATE)         // 14592
#define SMEM_BYTES (2 * BUFE * 2)    // 58368 bytes

template<int K, bool SPLIT_OUT>
__global__ __launch_bounds__(256, 2) void gemm_db_kernel(
    const __half* __restrict__ Wh, const __half* __restrict__ Wl,
    const __half* __restrict__ Ax,
    float* __restrict__ Of,
    __half* __restrict__ Oh, __half* __restrict__ Ol,
    int OCtot)
{
    extern __shared__ __align__(16) uint16_t dynsmem[];
    const uint32_t uS = smem_u32(dynsmem);

    const int tid  = threadIdx.x;
    const int warp = tid >> 5;
    const int lane = tid & 31;
    const int s0 = blockIdx.x * 128;
    const int j0 = blockIdx.y * 128;
    const int b  = blockIdx.z;

    const __half* Ap = Ax + (long long)b * K * HW;
    const long long obase = ((long long)b * OCtot + j0) * HW + s0;

    const int mbase = (warp >> 1) * 32;
    const int nbase = (warp & 1) * 64;

    float acc[64];
    #pragma unroll
    for (int i = 0; i < 64; i++) acc[i] = 0.f;

    const int lrow  = (lane & 7) + ((lane >> 3) & 1) * 8;
    const int lhalf = lane >> 4;

    const int wj = tid >> 2, wq = tid & 3;
    const int ak = tid >> 4, ag = tid & 15;

    auto stage = [&](int kc, int buf) {
        const uint32_t bWh = uS + (uint32_t)(buf * BUFE) * 2;
        const uint32_t bWl = bWh + WTE * 2;
        const uint32_t bAh = bWl + WTE * 2;
        const int k0 = kc * 32;
        #pragma unroll
        for (int i = 0; i < 2; i++) {
            int j = wj + i * 64;
            uint32_t d = (uint32_t)(j * WPITCH + wq * 8) * 2;
            long long g = (long long)(j0 + j) * K + k0 + wq * 8;
            cp16(bWh + d, Wh + g);
            cp16(bWl + d, Wl + g);
        }
        #pragma unroll
        for (int i = 0; i < 2; i++) {
            int kk = ak + i * 16;
            uint32_t d = (uint32_t)(kk * APITCH + ag * 8) * 2;
            long long g = (long long)(k0 + kk) * HW + s0 + ag * 8;
            cp16(bAh + d, Ap + g);
        }
        CP_COMMIT();
    };

    const int NK = K / 32;
    stage(0, 0);

    for (int kc = 0; kc < NK; kc++) {
        const int buf = kc & 1;
        if (kc + 1 < NK) {
            stage(kc + 1, (kc + 1) & 1);
            CP_WAIT1();
        } else {
            CP_WAIT0();
        }
        __syncthreads();

        const uint32_t bWh = uS + (uint32_t)(buf * BUFE) * 2;
        const uint32_t bWl = bWh + WTE * 2;
        const uint32_t bAh = bWl + WTE * 2;

        #pragma unroll
        for (int kh = 0; kh < 2; kh++) {
            uint32_t ah[2][4], al[2][4];
            #pragma unroll
            for (int mt = 0; mt < 2; mt++) {
                uint32_t off = (uint32_t)((mbase + mt * 16 + lrow) * (WPITCH * 2)
                                          + kh * 32 + lhalf * 16);
                ldsm_x4(ah[mt], bWh + off);
                ldsm_x4(al[mt], bWl + off);
            }
            #pragma unroll
            for (int np = 0; np < 4; np++) {
                uint32_t boff = (uint32_t)((kh * 16 + lrow) * (APITCH * 2)
                                           + (nbase + np * 16 + lhalf * 8) * 2);
                uint32_t bf[4];
                ldsm_x4_t(bf, bAh + boff);
                #pragma unroll
                for (int nt2 = 0; nt2 < 2; nt2++) {
                    const uint32_t b0 = bf[nt2 * 2], b1 = bf[nt2 * 2 + 1];
                    const int nt = np * 2 + nt2;
                    #pragma unroll
                    for (int mt = 0; mt < 2; mt++) {
                        float* cp = acc + (mt * 8 + nt) * 4;
                        mma_f16(cp, ah[mt], b0, b1);
                        mma_f16(cp, al[mt], b0, b1);
                    }
                }
            }
        }
        __syncthreads();
    }

    // ---- epilogue ----
    const int crow = lane >> 2;
    const int ccol = (lane & 3) * 2;
    #pragma unroll
    for (int mt = 0; mt < 2; mt++) {
        #pragma unroll
        for (int nt = 0; nt < 8; nt++) {
            const float* cp = acc + (mt * 8 + nt) * 4;
            long long r0 = obase + (long long)(mbase + mt * 16 + crow) * HW
                         + nbase + nt * 8 + ccol;
            long long r1 = r0 + 8 * HW;
            if (SPLIT_OUT) {
                uint32_t h0, l0, h1, l1;
                split_pack_h(cp[0], cp[1], h0, l0);
                split_pack_h(cp[2], cp[3], h1, l1);
                *(uint32_t*)&Oh[r0] = h0;  *(uint32_t*)&Ol[r0] = l0;
                *(uint32_t*)&Oh[r1] = h1;  *(uint32_t*)&Ol[r1] = l1;
            } else {
                *(float2*)&Of[r0] = make_float2(cp[0], cp[1]);
                *(float2*)&Of[r1] = make_float2(cp[2], cp[3]);
            }
        }
    }
}

// ---------------------------------------------------------------------------
// qk_mma: S_partial = Q K^T over a 512-spatial slice (fp16 3-term MMA)
// + per-row sumsq partials. grid = (NCHUNK_QK, B*HD), 256 threads.
// ---------------------------------------------------------------------------
#define QKP 136
#define QK_ARR (48 * QKP)
#define QK_SMEM (4 * QK_ARR * 2)

__global__ __launch_bounds__(256) void qk_mma_kernel(
    const __half* __restrict__ qh, const __half* __restrict__ ql,
    const __half* __restrict__ kh, const __half* __restrict__ kl,
    float* __restrict__ Sp, float* __restrict__ ssp)
{
    extern __shared__ __align__(16) uint16_t dynsmem[];
    __shared__ float Sred[DC][DC + 1];

    const uint32_t uQh = smem_u32(dynsmem);
    const uint32_t uQl = uQh + QK_ARR * 2;
    const uint32_t uKh = uQl + QK_ARR * 2;
    const uint32_t uKl = uKh + QK_ARR * 2;

    const int chunk = blockIdx.x;
    const int bh = blockIdx.y;
    const int b  = bh >> 3;
    const int h  = bh & 7;
    const long long qbase = ((long long)b * C   + h * DC) * HW;
    const long long kbase = ((long long)b * KVC + h * DC) * HW;
    const int sbase = chunk * (HW / NCHUNK_QK);

    const int tid  = threadIdx.x;
    const int warp = tid >> 5;
    const int lane = tid & 31;
    const int lrow  = (lane & 7) + ((lane >> 3) & 1) * 8;
    const int lhalf = lane >> 4;
    const int brow = ((lane >> 4) << 3) + (lane & 7);
    const int bcol = ((lane >> 3) & 1) * 8;

    const int kcol = warp * 16;

    float acc[72];
    #pragma unroll
    for (int i = 0; i < 72; i++) acc[i] = 0.f;
    float ssq = 0.f;

    for (int it = 0; it < 4; it++) {
        const int s0 = sbase + it * 128;
        #pragma unroll
        for (int i = 0; i < 3; i++) {
            int idx = i * 256 + tid;
            int row = idx >> 4, g = idx & 15;
            uint32_t d = (uint32_t)(row * QKP + g * 8) * 2;
            long long gq = qbase + (long long)row * HW + s0 + g * 8;
            long long gk = kbase + (long long)row * HW + s0 + g * 8;
            cp16(uQh + d, qh + gq);
            cp16(uQl + d, ql + gq);
            cp16(uKh + d, kh + gk);
            cp16(uKl + d, kl + gk);
        }
        CP_COMMIT();
        CP_WAIT0();
        __syncthreads();

        uint32_t bhf[12], blf[12];
        #pragma unroll
        for (int g = 0; g < 3; g++) {
            uint32_t off = (uint32_t)((g * 16 + brow) * QKP + kcol + bcol) * 2;
            ldsm_x4(&bhf[g * 4], uKh + off);
            ldsm_x4(&blf[g * 4], uKl + off);
        }
        #pragma unroll
        for (int mt = 0; mt < 3; mt++) {
            uint32_t ah[4], al[4];
            uint32_t off = (uint32_t)((mt * 16 + lrow) * QKP + kcol + lhalf * 8) * 2;
            ldsm_x4(ah, uQh + off);
            ldsm_x4(al, uQl + off);
            #pragma unroll
            for (int n8 = 0; n8 < 6; n8++) {
                float* cp = acc + (mt * 6 + n8) * 4;
                const uint32_t b0h = bhf[n8 * 2], b1h = bhf[n8 * 2 + 1];
                mma_f16(cp, ah, b0h, b1h);
                mma_f16(cp, ah, blf[n8 * 2], blf[n8 * 2 + 1]);
                mma_f16(cp, al, b0h, b1h);
            }
        }

        if (tid < 2 * DC) {
            const int r = (tid < DC) ? tid : tid - DC;
            const uint16_t* ph = (const uint16_t*)dynsmem
                               + (tid < DC ? 0 : 2 * QK_ARR) + r * QKP;
            const uint16_t* pl = ph + QK_ARR;
            #pragma unroll 8
            for (int g = 0; g < 64; g++) {
                uint32_t vh = *(const uint32_t*)(ph + g * 2);
                uint32_t vl = *(const uint32_t*)(pl + g * 2);
                float a = rec2h(vh, vl, 0);
                float c = rec2h(vh, vl, 1);
                ssq = fmaf(a, a, ssq);
                ssq = fmaf(c, c, ssq);
            }
        }
        __syncthreads();
    }

    for (int i = tid; i < DC * DC; i += 256) Sred[i / DC][i % DC] = 0.f;
    __syncthreads();
    const int crow = lane >> 2;
    const int ccol = (lane & 3) * 2;
    #pragma unroll
    for (int mt = 0; mt < 3; mt++) {
        #pragma unroll
        for (int n8 = 0; n8 < 6; n8++) {
            const float* cp = acc + (mt * 6 + n8) * 4;
            int r0 = mt * 16 + crow, c0 = n8 * 8 + ccol;
            atomicAdd(&Sred[r0][c0],     cp[0]);
            atomicAdd(&Sred[r0][c0 + 1], cp[1]);
            atomicAdd(&Sred[r0 + 8][c0],     cp[2]);
            atomicAdd(&Sred[r0 + 8][c0 + 1], cp[3]);
        }
    }
    __syncthreads();

    float* Sout = Sp + ((long long)chunk * (B * HD) + bh) * (DC * DC);
    for (int i = tid; i < DC * DC; i += 256)
        Sout[i] = Sred[i / DC][i % DC];
    if (tid < 2 * DC)
        ssp[((long long)chunk * (B * HD) + bh) * (2 * DC) + tid] = ssq;
}

// ---------------------------------------------------------------------------
// Reduce partials, norms + temperature, softmax; write S as fp16 hi/lo.
// ---------------------------------------------------------------------------
__global__ __launch_bounds__(256) void softmax_kernel(
    const float* __restrict__ Sp, const float* __restrict__ ssp,
    const float* __restrict__ temperature,
    __half* __restrict__ ShG, __half* __restrict__ SlG)
{
    const int bh = blockIdx.x;
    const int h  = bh & 7;
    const int tid = threadIdx.x;

    __shared__ float S[DC][DC + 1];
    __shared__ float invq[DC], invk[DC];

    for (int i = tid; i < DC * DC; i += 256) {
        float s = 0.f;
        #pragma unroll
        for (int ch = 0; ch < NCHUNK_QK; ch++)
            s += Sp[((long long)ch * (B * HD) + bh) * (DC * DC) + i];
        S[i / DC][i % DC] = s;
    }
    if (tid < 2 * DC) {
        float s = 0.f;
        #pragma unroll
        for (int ch = 0; ch < NCHUNK_QK; ch++)
            s += ssp[((long long)ch * (B * HD) + bh) * (2 * DC) + tid];
        float inv = 1.0f / fmaxf(sqrtf(s), 1e-12f);
        if (tid < DC) invq[tid] = inv; else invk[tid - DC] = inv;
    }
    __syncthreads();

    if (tid < DC) {
        const float t = temperature[h];
        const float iq = invq[tid] * t;
        float m = -INFINITY;
        float row[DC];
        #pragma unroll 8
        for (int d = 0; d < DC; d++) {
            float v = S[tid][d] * iq * invk[d];
            row[d] = v;
            m = fmaxf(m, v);
        }
        float sum = 0.f;
        #pragma unroll 8
        for (int d = 0; d < DC; d++) {
            float e = expf(row[d] - m);
            row[d] = e;
            sum += e;
        }
        float inv = 1.0f / sum;
        uint32_t* oh = (uint32_t*)(ShG + (long long)bh * (DC * DC) + tid * DC);
        uint32_t* ol = (uint32_t*)(SlG + (long long)bh * (DC * DC) + tid * DC);
        #pragma unroll
        for (int d = 0; d < DC; d += 2) {
            uint32_t ph, pl;
            split_pack_h(row[d] * inv, row[d + 1] * inv, ph, pl);
            oh[d / 2] = ph;
            ol[d / 2] = pl;
        }
    }
}

// ---------------------------------------------------------------------------
// sv_mma: O = S * V (fp16 3-term, K=48). Writes oh (1-limb) for GEMM3.
// grid = (NCHUNK_SV, B*HD).
// ---------------------------------------------------------------------------
#define SPITCH 56
#define VPITCH 136

__global__ __launch_bounds__(256) void sv_mma_kernel(
    const __half* __restrict__ ShG, const __half* __restrict__ SlG,
    const __half* __restrict__ vh, const __half* __restrict__ vl,
    __half* __restrict__ oh)
{
    __shared__ __align__(16) uint16_t sSh[DC * SPITCH];
    __shared__ __align__(16) uint16_t sSl[DC * SPITCH];
    __shared__ __align__(16) uint16_t sVh[DC * VPITCH];
    __shared__ __align__(16) uint16_t sVl[DC * VPITCH];

    const int chunk = blockIdx.x;
    const int bh = blockIdx.y;
    const int b  = bh >> 3;
    const int h  = bh & 7;
    const long long vbase = ((long long)b * KVC + C + h * DC) * HW;
    const long long obase = ((long long)b * C + h * DC) * HW;
    const int sbase = chunk * (HW / NCHUNK_SV);

    const int tid  = threadIdx.x;
    const int warp = tid >> 5;
    const int lane = tid & 31;
    const int lrow  = (lane & 7) + ((lane >> 3) & 1) * 8;
    const int lhalf = lane >> 4;
    const int crow = lane >> 2;
    const int ccol = (lane & 3) * 2;

    const uint32_t uSh = smem_u32(sSh);
    const uint32_t uSl = smem_u32(sSl);
    const uint32_t uVh = smem_u32(sVh);
    const uint32_t uVl = smem_u32(sVl);

    for (int idx = tid; idx < 288; idx += 256) {
        int row = idx / 6, g = idx % 6;
        uint32_t d = (uint32_t)(row * SPITCH + g * 8) * 2;
        long long s = (long long)bh * (DC * DC) + row * DC + g * 8;
        cp16(uSh + d, ShG + s);
        cp16(uSl + d, SlG + s);
    }

    const int n0w = warp * 16;

    for (int it = 0; it < 2; it++) {
        const int s0 = sbase + it * 128;
        #pragma unroll
        for (int i = 0; i < 3; i++) {
            int idx = i * 256 + tid;
            int row = idx >> 4, g = idx & 15;
            uint32_t d = (uint32_t)(row * VPITCH + g * 8) * 2;
            long long gsrc = vbase + (long long)row * HW + s0 + g * 8;
            cp16(uVh + d, vh + gsrc);
            cp16(uVl + d, vl + gsrc);
        }
        CP_COMMIT();
        CP_WAIT0();
        __syncthreads();

        float acc[24];
        #pragma unroll
        for (int i = 0; i < 24; i++) acc[i] = 0.f;

        #pragma unroll
        for (int ks = 0; ks < 3; ks++) {
            uint32_t bhf[4], blf[4];
            uint32_t boff = (uint32_t)((ks * 16 + lrow) * VPITCH
                                       + n0w + lhalf * 8) * 2;
            ldsm_x4_t(bhf, uVh + boff);
            ldsm_x4_t(blf, uVl + boff);
            #pragma unroll
            for (int mt = 0; mt < 3; mt++) {
                uint32_t ah[4], al[4];
                uint32_t aoff = (uint32_t)((mt * 16 + lrow) * SPITCH
                                           + ks * 16 + lhalf * 8) * 2;
                ldsm_x4(ah, uSh + aoff);
                ldsm_x4(al, uSl + aoff);
                #pragma unroll
                for (int nt2 = 0; nt2 < 2; nt2++) {
                    float* cp = acc + (mt * 2 + nt2) * 4;
                    const uint32_t b0 = bhf[nt2 * 2], b1 = bhf[nt2 * 2 + 1];
                    mma_f16(cp, ah, b0, b1);
                    mma_f16(cp, ah, blf[nt2 * 2], blf[nt2 * 2 + 1]);
                    mma_f16(cp, al, b0, b1);
                }
            }
        }

        #pragma unroll
        for (int mt = 0; mt < 3; mt++) {
            #pragma unroll
            for (int nt2 = 0; nt2 < 2; nt2++) {
                const float* cp = acc + (mt * 2 + nt2) * 4;
                int cc = mt * 16 + crow;
                int ss = s0 + n0w + nt2 * 8 + ccol;
                long long r0 = obase + (long long)cc * HW + ss;
                long long r1 = r0 + 8 * HW;
                *(uint32_t*)&oh[r0] = pack_h2(cp[0], cp[1]);
                *(uint32_t*)&oh[r1] = pack_h2(cp[2], cp[3]);
            }
        }
        __syncthreads();
    }
}

// ---------------------------------------------------------------------------
// Launch
// ---------------------------------------------------------------------------
extern "C" void kernel_launch(void* const* d_in, const int* in_sizes, int n_in,
                              void* d_out, int out_size)
{
    const float* x           = (const float*)d_in[0];
    const float* query       = (const float*)d_in[1];
    const float* w_kv        = (const float*)d_in[2];
    const float* w_q         = (const float*)d_in[3];
    const float* w_proj      = (const float*)d_in[4];
    const float* temperature = (const float*)d_in[5];
    float* out = (float*)d_out;

    float *Sp, *ssp;
    cudaGetSymbolAddress((void**)&Sp,  g_Sp);
    cudaGetSymbolAddress((void**)&ssp, g_ssp);

    __half *wkvh, *wkvl, *wqh, *wql, *wph, *wpl, *xh, *qrh;
    __half *kvh, *kvl, *qh, *ql, *oh, *Sh, *Sl;
    cudaGetSymbolAddress((void**)&wkvh, g_wkvh);
    cudaGetSymbolAddress((void**)&wkvl, g_wkvl);
    cudaGetSymbolAddress((void**)&wqh,  g_wqh);
    cudaGetSymbolAddress((void**)&wql,  g_wql);
    cudaGetSymbolAddress((void**)&wph,  g_wph);
    cudaGetSymbolAddress((void**)&wpl,  g_wpl);
    cudaGetSymbolAddress((void**)&xh,   g_xh);
    cudaGetSymbolAddress((void**)&qrh,  g_qrh);
    cudaGetSymbolAddress((void**)&kvh,  g_kvh);
    cudaGetSymbolAddress((void**)&kvl,  g_kvl);
    cudaGetSymbolAddress((void**)&qh,   g_qh);
    cudaGetSymbolAddress((void**)&ql,   g_ql);
    cudaGetSymbolAddress((void**)&oh,   g_oh);
    cudaGetSymbolAddress((void**)&Sh,   g_Sh);
    cudaGetSymbolAddress((void**)&Sl,   g_Sl);

    cudaFuncSetAttribute(gemm_db_kernel<C, true>,
                         cudaFuncAttributeMaxDynamicSharedMemorySize, SMEM_BYTES);
    cudaFuncSetAttribute(gemm_db_kernel<QC, true>,
                         cudaFuncAttributeMaxDynamicSharedMemorySize, SMEM_BYTES);
    cudaFuncSetAttribute(gemm_db_kernel<C, false>,
                         cudaFuncAttributeMaxDynamicSharedMemorySize, SMEM_BYTES);
    cudaFuncSetAttribute(qk_mma_kernel,
                         cudaFuncAttributeMaxDynamicSharedMemorySize, QK_SMEM);

    // 0) pre-split inputs (weights: 2-limb; activations: hi only)
    {
        int n4;
        n4 = KVC * C / 4;
        split2_kernel<<<(n4 + 255) / 256, 256>>>(w_kv, wkvh, wkvl, n4);
        n4 = C * QC / 4;
        split2_kernel<<<(n4 + 255) / 256, 256>>>(w_q, wqh, wql, n4);
        n4 = C * C / 4;
        split2_kernel<<<(n4 + 255) / 256, 256>>>(w_proj, wph, wpl, n4);
        n4 = (int)((long long)B * C * HW / 4);
        split1_kernel<<<(n4 + 255) / 256, 256>>>(x, xh, n4);
        n4 = (int)((long long)B * QC * HW / 4);
        split1_kernel<<<(n4 + 255) / 256, 256>>>(query, qrh, n4);
    }

    // 1) kv = w_kv @ x  -> fp16 hi/lo
    gemm_db_kernel<C, true><<<dim3(HW / 128, KVC / 128, B), 256, SMEM_BYTES>>>(
        wkvh, wkvl, xh, nullptr, kvh, kvl, KVC);

    // 2) q = w_q @ query -> fp16 hi/lo
    gemm_db_kernel<QC, true><<<dim3(HW / 128, C / 128, B), 256, SMEM_BYTES>>>(
        wqh, wql, qrh, nullptr, qh, ql, C);

    // 3) QK^T partials + sumsq (tensor cores, 3-term fp16)
    qk_mma_kernel<<<dim3(NCHUNK_QK, B * HD), 256, QK_SMEM>>>(
        qh, ql, kvh, kvl, Sp, ssp);

    // 4) reduce + norm-scale + softmax -> S hi/lo
    softmax_kernel<<<B * HD, 256>>>(Sp, ssp, temperature, Sh, Sl);

    // 5) O = S * V (tensor cores) -> fp16 hi
    sv_mma_kernel<<<dim3(NCHUNK_SV, B * HD), 256>>>(Sh, Sl, kvh, kvl, oh);

    // 6) out = w_proj @ o -> fp32
    gemm_db_kernel<C, false><<<dim3(HW / 128, C / 128, B), 256, SMEM_BYTES>>>(
        wph, wpl, oh, out, nullptr, nullptr, C);
}

// round 14
// speedup vs baseline: 1.9825x; 1.2349x over previous
#include <cuda_runtime.h>
#include <cuda_fp16.h>
#include <math.h>
#include <stdint.h>

// Problem constants
#define B   16
#define C   384
#define HD  8
#define DC  48
#define HW  4096
#define QC  192
#define KVC 768

#define NCHUNK_QK 8
#define NCHUNK_SV 16

// Scratch (device globals)
__device__ float g_Sp [NCHUNK_QK * B * HD * DC * DC];
__device__ float g_ssp[NCHUNK_QK * B * HD * 2 * DC];

// fp16 operand buffers (weights + input acts: 1-limb; kv/q: 2-limb)
__device__ __half g_wkv[KVC * C];
__device__ __half g_wq [C * QC];
__device__ __half g_wp [C * C];
__device__ __half g_xh [(long long)B * C  * HW];
__device__ __half g_qrh[(long long)B * QC * HW];
__device__ __half g_kvh[(long long)B * KVC * HW], g_kvl[(long long)B * KVC * HW];
__device__ __half g_qh [(long long)B * C  * HW], g_ql [(long long)B * C  * HW];
__device__ __half g_oh [(long long)B * C  * HW];
__device__ __half g_Sh [B * HD * DC * DC], g_Sl [B * HD * DC * DC];

// ---------------------------------------------------------------------------
// PTX helpers
// ---------------------------------------------------------------------------
__device__ __forceinline__ uint32_t smem_u32(const void* p) {
    uint32_t a;
    asm("{ .reg .u64 t; cvta.to.shared.u64 t, %1; cvt.u32.u64 %0, t; }" : "=r"(a) : "l"(p));
    return a;
}
__device__ __forceinline__ void cp16(uint32_t dst, const void* src) {
    asm volatile("cp.async.ca.shared.global [%0], [%1], 16;" :: "r"(dst), "l"(src));
}
#define CP_COMMIT() asm volatile("cp.async.commit_group;" ::: "memory")
#define CP_WAIT0()  asm volatile("cp.async.wait_group 0;" ::: "memory")
#define CP_WAIT1()  asm volatile("cp.async.wait_group 1;" ::: "memory")

__device__ __forceinline__ void ldsm_x4(uint32_t r[4], uint32_t addr) {
    asm volatile("ldmatrix.sync.aligned.m8n8.x4.shared.b16 {%0,%1,%2,%3}, [%4];"
                 : "=r"(r[0]), "=r"(r[1]), "=r"(r[2]), "=r"(r[3]) : "r"(addr));
}
__device__ __forceinline__ void ldsm_x4_t(uint32_t r[4], uint32_t addr) {
    asm volatile("ldmatrix.sync.aligned.m8n8.x4.trans.shared.b16 {%0,%1,%2,%3}, [%4];"
                 : "=r"(r[0]), "=r"(r[1]), "=r"(r[2]), "=r"(r[3]) : "r"(addr));
}
__device__ __forceinline__ void mma_f16(float* c, const uint32_t a[4],
                                        uint32_t b0, uint32_t b1) {
    asm volatile(
        "mma.sync.aligned.m16n8k16.row.col.f32.f16.f16.f32 "
        "{%0,%1,%2,%3}, {%4,%5,%6,%7}, {%8,%9}, {%0,%1,%2,%3};"
        : "+f"(c[0]), "+f"(c[1]), "+f"(c[2]), "+f"(c[3])
        : "r"(a[0]), "r"(a[1]), "r"(a[2]), "r"(a[3]), "r"(b0), "r"(b1));
}

// fp16 hi/lo split: x ~= hi + lo
__device__ __forceinline__ void split_pack_h(float x0, float x1,
                                             uint32_t& ph, uint32_t& pl) {
    __half h0 = __float2half_rn(x0);
    __half h1 = __float2half_rn(x1);
    __half l0 = __float2half_rn(x0 - __half2float(h0));
    __half l1 = __float2half_rn(x1 - __half2float(h1));
    ph = (uint32_t)__half_as_ushort(h0) | ((uint32_t)__half_as_ushort(h1) << 16);
    pl = (uint32_t)__half_as_ushort(l0) | ((uint32_t)__half_as_ushort(l1) << 16);
}
__device__ __forceinline__ uint32_t pack_h2(float x0, float x1) {
    return (uint32_t)__half_as_ushort(__float2half_rn(x0))
         | ((uint32_t)__half_as_ushort(__float2half_rn(x1)) << 16);
}
__device__ __forceinline__ float rec2h(uint32_t ph, uint32_t pl, int half) {
    uint16_t h = half ? (uint16_t)(ph >> 16) : (uint16_t)ph;
    uint16_t l = half ? (uint16_t)(pl >> 16) : (uint16_t)pl;
    return __half2float(__ushort_as_half(h)) + __half2float(__ushort_as_half(l));
}

// fp32 -> fp16 (round-to-nearest), 4 elems/thread
__global__ __launch_bounds__(256) void split1_kernel(
    const float* __restrict__ src, __half* __restrict__ dh, int n4)
{
    int i = blockIdx.x * 256 + threadIdx.x;
    if (i < n4) {
        float4 v = ((const float4*)src)[i];
        ((uint2*)dh)[i] = make_uint2(pack_h2(v.x, v.y), pack_h2(v.z, v.w));
    }
}

// ---------------------------------------------------------------------------
// fp16 1-term tensor-core GEMM: Out[b][j][s] = sum_k W[j][k] * Act[b][k][s]
// Both operands 1-limb fp16, fp32 accumulate.
// CTA tile 128(j) x 128(s), K-chunk 32, 8 warps (4m x 2n), double-buffered.
// ---------------------------------------------------------------------------
#define WPITCH 40
#define APITCH 136
#define WTE (128 * WPITCH)           // 5120
#define ATE (32 * APITCH)            // 4352
#define BUFE (WTE + ATE)             // 9472
#define SMEM_BYTES (2 * BUFE * 2)    // 37888 bytes

template<int K, bool SPLIT_OUT>
__global__ __launch_bounds__(256, 2) void gemm_db_kernel(
    const __half* __restrict__ W,
    const __half* __restrict__ Ax,
    float* __restrict__ Of,
    __half* __restrict__ Oh, __half* __restrict__ Ol,
    int OCtot)
{
    extern __shared__ __align__(16) uint16_t dynsmem[];
    const uint32_t uS = smem_u32(dynsmem);

    const int tid  = threadIdx.x;
    const int warp = tid >> 5;
    const int lane = tid & 31;
    const int s0 = blockIdx.x * 128;
    const int j0 = blockIdx.y * 128;
    const int b  = blockIdx.z;

    const __half* Ap = Ax + (long long)b * K * HW;
    const long long obase = ((long long)b * OCtot + j0) * HW + s0;

    const int mbase = (warp >> 1) * 32;
    const int nbase = (warp & 1) * 64;

    float acc[64];
    #pragma unroll
    for (int i = 0; i < 64; i++) acc[i] = 0.f;

    const int lrow  = (lane & 7) + ((lane >> 3) & 1) * 8;
    const int lhalf = lane >> 4;

    const int wj = tid >> 2, wq = tid & 3;
    const int ak = tid >> 4, ag = tid & 15;

    auto stage = [&](int kc, int buf) {
        const uint32_t bW = uS + (uint32_t)(buf * BUFE) * 2;
        const uint32_t bA = bW + WTE * 2;
        const int k0 = kc * 32;
        #pragma unroll
        for (int i = 0; i < 2; i++) {
            int j = wj + i * 64;
            uint32_t d = (uint32_t)(j * WPITCH + wq * 8) * 2;
            cp16(bW + d, W + (long long)(j0 + j) * K + k0 + wq * 8);
        }
        #pragma unroll
        for (int i = 0; i < 2; i++) {
            int kk = ak + i * 16;
            uint32_t d = (uint32_t)(kk * APITCH + ag * 8) * 2;
            cp16(bA + d, Ap + (long long)(k0 + kk) * HW + s0 + ag * 8);
        }
        CP_COMMIT();
    };

    const int NK = K / 32;
    stage(0, 0);

    for (int kc = 0; kc < NK; kc++) {
        const int buf = kc & 1;
        if (kc + 1 < NK) {
            stage(kc + 1, (kc + 1) & 1);
            CP_WAIT1();
        } else {
            CP_WAIT0();
        }
        __syncthreads();

        const uint32_t bW = uS + (uint32_t)(buf * BUFE) * 2;
        const uint32_t bA = bW + WTE * 2;

        #pragma unroll
        for (int kh = 0; kh < 2; kh++) {
            uint32_t ah[2][4];
            #pragma unroll
            for (int mt = 0; mt < 2; mt++) {
                uint32_t off = (uint32_t)((mbase + mt * 16 + lrow) * (WPITCH * 2)
                                          + kh * 32 + lhalf * 16);
                ldsm_x4(ah[mt], bW + off);
            }
            #pragma unroll
            for (int np = 0; np < 4; np++) {
                uint32_t boff = (uint32_t)((kh * 16 + lrow) * (APITCH * 2)
                                           + (nbase + np * 16 + lhalf * 8) * 2);
                uint32_t bf[4];
                ldsm_x4_t(bf, bA + boff);
                #pragma unroll
                for (int nt2 = 0; nt2 < 2; nt2++) {
                    const uint32_t b0 = bf[nt2 * 2], b1 = bf[nt2 * 2 + 1];
                    const int nt = np * 2 + nt2;
                    #pragma unroll
                    for (int mt = 0; mt < 2; mt++)
                        mma_f16(acc + (mt * 8 + nt) * 4, ah[mt], b0, b1);
                }
            }
        }
        __syncthreads();
    }

    // ---- epilogue ----
    const int crow = lane >> 2;
    const int ccol = (lane & 3) * 2;
    #pragma unroll
    for (int mt = 0; mt < 2; mt++) {
        #pragma unroll
        for (int nt = 0; nt < 8; nt++) {
            const float* cp = acc + (mt * 8 + nt) * 4;
            long long r0 = obase + (long long)(mbase + mt * 16 + crow) * HW
                         + nbase + nt * 8 + ccol;
            long long r1 = r0 + 8 * HW;
            if (SPLIT_OUT) {
                uint32_t h0, l0, h1, l1;
                split_pack_h(cp[0], cp[1], h0, l0);
                split_pack_h(cp[2], cp[3], h1, l1);
                *(uint32_t*)&Oh[r0] = h0;  *(uint32_t*)&Ol[r0] = l0;
                *(uint32_t*)&Oh[r1] = h1;  *(uint32_t*)&Ol[r1] = l1;
            } else {
                *(float2*)&Of[r0] = make_float2(cp[0], cp[1]);
                *(float2*)&Of[r1] = make_float2(cp[2], cp[3]);
            }
        }
    }
}

// ---------------------------------------------------------------------------
// qk_mma: S_partial = Q K^T over a 512-spatial slice (fp16 3-term MMA)
// + per-row sumsq partials. grid = (NCHUNK_QK, B*HD), 256 threads.
// ---------------------------------------------------------------------------
#define QKP 136
#define QK_ARR (48 * QKP)
#define QK_SMEM (4 * QK_ARR * 2)

__global__ __launch_bounds__(256) void qk_mma_kernel(
    const __half* __restrict__ qh, const __half* __restrict__ ql,
    const __half* __restrict__ kh, const __half* __restrict__ kl,
    float* __restrict__ Sp, float* __restrict__ ssp)
{
    extern __shared__ __align__(16) uint16_t dynsmem[];
    __shared__ float Sred[DC][DC + 1];

    const uint32_t uQh = smem_u32(dynsmem);
    const uint32_t uQl = uQh + QK_ARR * 2;
    const uint32_t uKh = uQl + QK_ARR * 2;
    const uint32_t uKl = uKh + QK_ARR * 2;

    const int chunk = blockIdx.x;
    const int bh = blockIdx.y;
    const int b  = bh >> 3;
    const int h  = bh & 7;
    const long long qbase = ((long long)b * C   + h * DC) * HW;
    const long long kbase = ((long long)b * KVC + h * DC) * HW;
    const int sbase = chunk * (HW / NCHUNK_QK);

    const int tid  = threadIdx.x;
    const int warp = tid >> 5;
    const int lane = tid & 31;
    const int lrow  = (lane & 7) + ((lane >> 3) & 1) * 8;
    const int lhalf = lane >> 4;
    const int brow = ((lane >> 4) << 3) + (lane & 7);
    const int bcol = ((lane >> 3) & 1) * 8;

    const int kcol = warp * 16;

    float acc[72];
    #pragma unroll
    for (int i = 0; i < 72; i++) acc[i] = 0.f;
    float ssq = 0.f;

    for (int it = 0; it < 4; it++) {
        const int s0 = sbase + it * 128;
        #pragma unroll
        for (int i = 0; i < 3; i++) {
            int idx = i * 256 + tid;
            int row = idx >> 4, g = idx & 15;
            uint32_t d = (uint32_t)(row * QKP + g * 8) * 2;
            long long gq = qbase + (long long)row * HW + s0 + g * 8;
            long long gk = kbase + (long long)row * HW + s0 + g * 8;
            cp16(uQh + d, qh + gq);
            cp16(uQl + d, ql + gq);
            cp16(uKh + d, kh + gk);
            cp16(uKl + d, kl + gk);
        }
        CP_COMMIT();
        CP_WAIT0();
        __syncthreads();

        uint32_t bhf[12], blf[12];
        #pragma unroll
        for (int g = 0; g < 3; g++) {
            uint32_t off = (uint32_t)((g * 16 + brow) * QKP + kcol + bcol) * 2;
            ldsm_x4(&bhf[g * 4], uKh + off);
            ldsm_x4(&blf[g * 4], uKl + off);
        }
        #pragma unroll
        for (int mt = 0; mt < 3; mt++) {
            uint32_t ah[4], al[4];
            uint32_t off = (uint32_t)((mt * 16 + lrow) * QKP + kcol + lhalf * 8) * 2;
            ldsm_x4(ah, uQh + off);
            ldsm_x4(al, uQl + off);
            #pragma unroll
            for (int n8 = 0; n8 < 6; n8++) {
                float* cp = acc + (mt * 6 + n8) * 4;
                const uint32_t b0h = bhf[n8 * 2], b1h = bhf[n8 * 2 + 1];
                mma_f16(cp, ah, b0h, b1h);
                mma_f16(cp, ah, blf[n8 * 2], blf[n8 * 2 + 1]);
                mma_f16(cp, al, b0h, b1h);
            }
        }

        if (tid < 2 * DC) {
            const int r = (tid < DC) ? tid : tid - DC;
            const uint16_t* ph = (const uint16_t*)dynsmem
                               + (tid < DC ? 0 : 2 * QK_ARR) + r * QKP;
            const uint16_t* pl = ph + QK_ARR;
            #pragma unroll 8
            for (int g = 0; g < 64; g++) {
                uint32_t vh = *(const uint32_t*)(ph + g * 2);
                uint32_t vl = *(const uint32_t*)(pl + g * 2);
                float a = rec2h(vh, vl, 0);
                float c = rec2h(vh, vl, 1);
                ssq = fmaf(a, a, ssq);
                ssq = fmaf(c, c, ssq);
            }
        }
        __syncthreads();
    }

    for (int i = tid; i < DC * DC; i += 256) Sred[i / DC][i % DC] = 0.f;
    __syncthreads();
    const int crow = lane >> 2;
    const int ccol = (lane & 3) * 2;
    #pragma unroll
    for (int mt = 0; mt < 3; mt++) {
        #pragma unroll
        for (int n8 = 0; n8 < 6; n8++) {
            const float* cp = acc + (mt * 6 + n8) * 4;
            int r0 = mt * 16 + crow, c0 = n8 * 8 + ccol;
            atomicAdd(&Sred[r0][c0],     cp[0]);
            atomicAdd(&Sred[r0][c0 + 1], cp[1]);
            atomicAdd(&Sred[r0 + 8][c0],     cp[2]);
            atomicAdd(&Sred[r0 + 8][c0 + 1], cp[3]);
        }
    }
    __syncthreads();

    float* Sout = Sp + ((long long)chunk * (B * HD) + bh) * (DC * DC);
    for (int i = tid; i < DC * DC; i += 256)
        Sout[i] = Sred[i / DC][i % DC];
    if (tid < 2 * DC)
        ssp[((long long)chunk * (B * HD) + bh) * (2 * DC) + tid] = ssq;
}

// ---------------------------------------------------------------------------
// Reduce partials, norms + temperature, softmax; write S as fp16 hi/lo.
// ---------------------------------------------------------------------------
__global__ __launch_bounds__(256) void softmax_kernel(
    const float* __restrict__ Sp, const float* __restrict__ ssp,
    const float* __restrict__ temperature,
    __half* __restrict__ ShG, __half* __restrict__ SlG)
{
    const int bh = blockIdx.x;
    const int h  = bh & 7;
    const int tid = threadIdx.x;

    __shared__ float S[DC][DC + 1];
    __shared__ float invq[DC], invk[DC];

    for (int i = tid; i < DC * DC; i += 256) {
        float s = 0.f;
        #pragma unroll
        for (int ch = 0; ch < NCHUNK_QK; ch++)
            s += Sp[((long long)ch * (B * HD) + bh) * (DC * DC) + i];
        S[i / DC][i % DC] = s;
    }
    if (tid < 2 * DC) {
        float s = 0.f;
        #pragma unroll
        for (int ch = 0; ch < NCHUNK_QK; ch++)
            s += ssp[((long long)ch * (B * HD) + bh) * (2 * DC) + tid];
        float inv = 1.0f / fmaxf(sqrtf(s), 1e-12f);
        if (tid < DC) invq[tid] = inv; else invk[tid - DC] = inv;
    }
    __syncthreads();

    if (tid < DC) {
        const float t = temperature[h];
        const float iq = invq[tid] * t;
        float m = -INFINITY;
        float row[DC];
        #pragma unroll 8
        for (int d = 0; d < DC; d++) {
            float v = S[tid][d] * iq * invk[d];
            row[d] = v;
            m = fmaxf(m, v);
        }
        float sum = 0.f;
        #pragma unroll 8
        for (int d = 0; d < DC; d++) {
            float e = expf(row[d] - m);
            row[d] = e;
            sum += e;
        }
        float inv = 1.0f / sum;
        uint32_t* oh = (uint32_t*)(ShG + (long long)bh * (DC * DC) + tid * DC);
        uint32_t* ol = (uint32_t*)(SlG + (long long)bh * (DC * DC) + tid * DC);
        #pragma unroll
        for (int d = 0; d < DC; d += 2) {
            uint32_t ph, pl;
            split_pack_h(row[d] * inv, row[d + 1] * inv, ph, pl);
            oh[d / 2] = ph;
            ol[d / 2] = pl;
        }
    }
}

// ---------------------------------------------------------------------------
// sv_mma: O = S * V (fp16 3-term, K=48). Writes oh (1-limb) for GEMM3.
// grid = (NCHUNK_SV, B*HD).
// ---------------------------------------------------------------------------
#define SPITCH 56
#define VPITCH 136

__global__ __launch_bounds__(256) void sv_mma_kernel(
    const __half* __restrict__ ShG, const __half* __restrict__ SlG,
    const __half* __restrict__ vh, const __half* __restrict__ vl,
    __half* __restrict__ oh)
{
    __shared__ __align__(16) uint16_t sSh[DC * SPITCH];
    __shared__ __align__(16) uint16_t sSl[DC * SPITCH];
    __shared__ __align__(16) uint16_t sVh[DC * VPITCH];
    __shared__ __align__(16) uint16_t sVl[DC * VPITCH];

    const int chunk = blockIdx.x;
    const int bh = blockIdx.y;
    const int b  = bh >> 3;
    const int h  = bh & 7;
    const long long vbase = ((long long)b * KVC + C + h * DC) * HW;
    const long long obase = ((long long)b * C + h * DC) * HW;
    const int sbase = chunk * (HW / NCHUNK_SV);

    const int tid  = threadIdx.x;
    const int warp = tid >> 5;
    const int lane = tid & 31;
    const int lrow  = (lane & 7) + ((lane >> 3) & 1) * 8;
    const int lhalf = lane >> 4;
    const int crow = lane >> 2;
    const int ccol = (lane & 3) * 2;

    const uint32_t uSh = smem_u32(sSh);
    const uint32_t uSl = smem_u32(sSl);
    const uint32_t uVh = smem_u32(sVh);
    const uint32_t uVl = smem_u32(sVl);

    for (int idx = tid; idx < 288; idx += 256) {
        int row = idx / 6, g = idx % 6;
        uint32_t d = (uint32_t)(row * SPITCH + g * 8) * 2;
        long long s = (long long)bh * (DC * DC) + row * DC + g * 8;
        cp16(uSh + d, ShG + s);
        cp16(uSl + d, SlG + s);
    }

    const int n0w = warp * 16;

    for (int it = 0; it < 2; it++) {
        const int s0 = sbase + it * 128;
        #pragma unroll
        for (int i = 0; i < 3; i++) {
            int idx = i * 256 + tid;
            int row = idx >> 4, g = idx & 15;
            uint32_t d = (uint32_t)(row * VPITCH + g * 8) * 2;
            long long gsrc = vbase + (long long)row * HW + s0 + g * 8;
            cp16(uVh + d, vh + gsrc);
            cp16(uVl + d, vl + gsrc);
        }
        CP_COMMIT();
        CP_WAIT0();
        __syncthreads();

        float acc[24];
        #pragma unroll
        for (int i = 0; i < 24; i++) acc[i] = 0.f;

        #pragma unroll
        for (int ks = 0; ks < 3; ks++) {
            uint32_t bhf[4], blf[4];
            uint32_t boff = (uint32_t)((ks * 16 + lrow) * VPITCH
                                       + n0w + lhalf * 8) * 2;
            ldsm_x4_t(bhf, uVh + boff);
            ldsm_x4_t(blf, uVl + boff);
            #pragma unroll
            for (int mt = 0; mt < 3; mt++) {
                uint32_t ah[4], al[4];
                uint32_t aoff = (uint32_t)((mt * 16 + lrow) * SPITCH
                                           + ks * 16 + lhalf * 8) * 2;
                ldsm_x4(ah, uSh + aoff);
                ldsm_x4(al, uSl + aoff);
                #pragma unroll
                for (int nt2 = 0; nt2 < 2; nt2++) {
                    float* cp = acc + (mt * 2 + nt2) * 4;
                    const uint32_t b0 = bhf[nt2 * 2], b1 = bhf[nt2 * 2 + 1];
                    mma_f16(cp, ah, b0, b1);
                    mma_f16(cp, ah, blf[nt2 * 2], blf[nt2 * 2 + 1]);
                    mma_f16(cp, al, b0, b1);
                }
            }
        }

        #pragma unroll
        for (int mt = 0; mt < 3; mt++) {
            #pragma unroll
            for (int nt2 = 0; nt2 < 2; nt2++) {
                const float* cp = acc + (mt * 2 + nt2) * 4;
                int cc = mt * 16 + crow;
                int ss = s0 + n0w + nt2 * 8 + ccol;
                long long r0 = obase + (long long)cc * HW + ss;
                long long r1 = r0 + 8 * HW;
                *(uint32_t*)&oh[r0] = pack_h2(cp[0], cp[1]);
                *(uint32_t*)&oh[r1] = pack_h2(cp[2], cp[3]);
            }
        }
        __syncthreads();
    }
}

// ---------------------------------------------------------------------------
// Launch
// ---------------------------------------------------------------------------
extern "C" void kernel_launch(void* const* d_in, const int* in_sizes, int n_in,
                              void* d_out, int out_size)
{
    const float* x           = (const float*)d_in[0];
    const float* query       = (const float*)d_in[1];
    const float* w_kv        = (const float*)d_in[2];
    const float* w_q         = (const float*)d_in[3];
    const float* w_proj      = (const float*)d_in[4];
    const float* temperature = (const float*)d_in[5];
    float* out = (float*)d_out;

    float *Sp, *ssp;
    cudaGetSymbolAddress((void**)&Sp,  g_Sp);
    cudaGetSymbolAddress((void**)&ssp, g_ssp);

    __half *wkv, *wq, *wp, *xh, *qrh;
    __half *kvh, *kvl, *qh, *ql, *oh, *Sh, *Sl;
    cudaGetSymbolAddress((void**)&wkv,  g_wkv);
    cudaGetSymbolAddress((void**)&wq,   g_wq);
    cudaGetSymbolAddress((void**)&wp,   g_wp);
    cudaGetSymbolAddress((void**)&xh,   g_xh);
    cudaGetSymbolAddress((void**)&qrh,  g_qrh);
    cudaGetSymbolAddress((void**)&kvh,  g_kvh);
    cudaGetSymbolAddress((void**)&kvl,  g_kvl);
    cudaGetSymbolAddress((void**)&qh,   g_qh);
    cudaGetSymbolAddress((void**)&ql,   g_ql);
    cudaGetSymbolAddress((void**)&oh,   g_oh);
    cudaGetSymbolAddress((void**)&Sh,   g_Sh);
    cudaGetSymbolAddress((void**)&Sl,   g_Sl);

    cudaFuncSetAttribute(gemm_db_kernel<C, true>,
                         cudaFuncAttributeMaxDynamicSharedMemorySize, SMEM_BYTES);
    cudaFuncSetAttribute(gemm_db_kernel<QC, true>,
                         cudaFuncAttributeMaxDynamicSharedMemorySize, SMEM_BYTES);
    cudaFuncSetAttribute(gemm_db_kernel<C, false>,
                         cudaFuncAttributeMaxDynamicSharedMemorySize, SMEM_BYTES);
    cudaFuncSetAttribute(qk_mma_kernel,
                         cudaFuncAttributeMaxDynamicSharedMemorySize, QK_SMEM);

    // 0) fp32 -> fp16 conversions (all 1-limb)
    {
        int n4;
        n4 = KVC * C / 4;
        split1_kernel<<<(n4 + 255) / 256, 256>>>(w_kv, wkv, n4);
        n4 = C * QC / 4;
        split1_kernel<<<(n4 + 255) / 256, 256>>>(w_q, wq, n4);
        n4 = C * C / 4;
        split1_kernel<<<(n4 + 255) / 256, 256>>>(w_proj, wp, n4);
        n4 = (int)((long long)B * C * HW / 4);
        split1_kernel<<<(n4 + 255) / 256, 256>>>(x, xh, n4);
        n4 = (int)((long long)B * QC * HW / 4);
        split1_kernel<<<(n4 + 255) / 256, 256>>>(query, qrh, n4);
    }

    // 1) kv = w_kv @ x  -> fp16 hi/lo
    gemm_db_kernel<C, true><<<dim3(HW / 128, KVC / 128, B), 256, SMEM_BYTES>>>(
        wkv, xh, nullptr, kvh, kvl, KVC);

    // 2) q = w_q @ query -> fp16 hi/lo
    gemm_db_kernel<QC, true><<<dim3(HW / 128, C / 128, B), 256, SMEM_BYTES>>>(
        wq, qrh, nullptr, qh, ql, C);

    // 3) QK^T partials + sumsq (tensor cores, 3-term fp16)
    qk_mma_kernel<<<dim3(NCHUNK_QK, B * HD), 256, QK_SMEM>>>(
        qh, ql, kvh, kvl, Sp, ssp);

    // 4) reduce + norm-scale + softmax -> S hi/lo
    softmax_kernel<<<B * HD, 256>>>(Sp, ssp, temperature, Sh, Sl);

    // 5) O = S * V (tensor cores) -> fp16 hi
    sv_mma_kernel<<<dim3(NCHUNK_SV, B * HD), 256>>>(Sh, Sl, kvh, kvl, oh);

    // 6) out = w_proj @ o -> fp32
    gemm_db_kernel<C, false><<<dim3(HW / 128, C / 128, B), 256, SMEM_BYTES>>>(
        wp, oh, out, nullptr, nullptr, C);
}

// round 15
// speedup vs baseline: 2.4039x; 1.2126x over previous
#include <cuda_runtime.h>
#include <cuda_fp16.h>
#include <math.h>
#include <stdint.h>

// Problem constants
#define B   16
#define C   384
#define HD  8
#define DC  48
#define HW  4096
#define QC  192
#define KVC 768

#define NCHUNK_QK 8
#define NCHUNK_SV 16

// Scratch (device globals)
__device__ float g_Sp [NCHUNK_QK * B * HD * DC * DC];
__device__ float g_ssp[NCHUNK_QK * B * HD * 2 * DC];

// fp16 operand buffers (ALL 1-limb)
__device__ __half g_wkv[KVC * C];
__device__ __half g_wq [C * QC];
__device__ __half g_wp [C * C];
__device__ __half g_xh [(long long)B * C  * HW];
__device__ __half g_qrh[(long long)B * QC * HW];
__device__ __half g_kvh[(long long)B * KVC * HW];
__device__ __half g_qh [(long long)B * C  * HW];
__device__ __half g_oh [(long long)B * C  * HW];
__device__ __half g_Sh [B * HD * DC * DC];

// ---------------------------------------------------------------------------
// PTX helpers
// ---------------------------------------------------------------------------
__device__ __forceinline__ uint32_t smem_u32(const void* p) {
    uint32_t a;
    asm("{ .reg .u64 t; cvta.to.shared.u64 t, %1; cvt.u32.u64 %0, t; }" : "=r"(a) : "l"(p));
    return a;
}
__device__ __forceinline__ void cp16(uint32_t dst, const void* src) {
    asm volatile("cp.async.ca.shared.global [%0], [%1], 16;" :: "r"(dst), "l"(src));
}
#define CP_COMMIT() asm volatile("cp.async.commit_group;" ::: "memory")
#define CP_WAIT0()  asm volatile("cp.async.wait_group 0;" ::: "memory")
#define CP_WAIT1()  asm volatile("cp.async.wait_group 1;" ::: "memory")

__device__ __forceinline__ void ldsm_x4(uint32_t r[4], uint32_t addr) {
    asm volatile("ldmatrix.sync.aligned.m8n8.x4.shared.b16 {%0,%1,%2,%3}, [%4];"
                 : "=r"(r[0]), "=r"(r[1]), "=r"(r[2]), "=r"(r[3]) : "r"(addr));
}
__device__ __forceinline__ void ldsm_x4_t(uint32_t r[4], uint32_t addr) {
    asm volatile("ldmatrix.sync.aligned.m8n8.x4.trans.shared.b16 {%0,%1,%2,%3}, [%4];"
                 : "=r"(r[0]), "=r"(r[1]), "=r"(r[2]), "=r"(r[3]) : "r"(addr));
}
__device__ __forceinline__ void mma_f16(float* c, const uint32_t a[4],
                                        uint32_t b0, uint32_t b1) {
    asm volatile(
        "mma.sync.aligned.m16n8k16.row.col.f32.f16.f16.f32 "
        "{%0,%1,%2,%3}, {%4,%5,%6,%7}, {%8,%9}, {%0,%1,%2,%3};"
        : "+f"(c[0]), "+f"(c[1]), "+f"(c[2]), "+f"(c[3])
        : "r"(a[0]), "r"(a[1]), "r"(a[2]), "r"(a[3]), "r"(b0), "r"(b1));
}

__device__ __forceinline__ uint32_t pack_h2(float x0, float x1) {
    return (uint32_t)__half_as_ushort(__float2half_rn(x0))
         | ((uint32_t)__half_as_ushort(__float2half_rn(x1)) << 16);
}
__device__ __forceinline__ float h_lo(uint32_t v) {
    return __half2float(__ushort_as_half((uint16_t)v));
}
__device__ __forceinline__ float h_hi(uint32_t v) {
    return __half2float(__ushort_as_half((uint16_t)(v >> 16)));
}

// fp32 -> fp16 (round-to-nearest), 4 elems/thread
__global__ __launch_bounds__(256) void split1_kernel(
    const float* __restrict__ src, __half* __restrict__ dh, int n4)
{
    int i = blockIdx.x * 256 + threadIdx.x;
    if (i < n4) {
        float4 v = ((const float4*)src)[i];
        ((uint2*)dh)[i] = make_uint2(pack_h2(v.x, v.y), pack_h2(v.z, v.w));
    }
}

// ---------------------------------------------------------------------------
// fp16 1-term tensor-core GEMM: Out[b][j][s] = sum_k W[j][k] * Act[b][k][s]
// CTA tile 128(j) x 128(s), K-chunk 32, 8 warps (4m x 2n), double-buffered.
// HALF_OUT: write fp16 (Oh) else fp32 (Of).
// ---------------------------------------------------------------------------
#define WPITCH 40
#define APITCH 136
#define WTE (128 * WPITCH)           // 5120
#define ATE (32 * APITCH)            // 4352
#define BUFE (WTE + ATE)             // 9472
#define SMEM_BYTES (2 * BUFE * 2)    // 37888 bytes

template<int K, bool HALF_OUT>
__global__ __launch_bounds__(256, 2) void gemm_db_kernel(
    const __half* __restrict__ W,
    const __half* __restrict__ Ax,
    float* __restrict__ Of,
    __half* __restrict__ Oh,
    int OCtot)
{
    extern __shared__ __align__(16) uint16_t dynsmem[];
    const uint32_t uS = smem_u32(dynsmem);

    const int tid  = threadIdx.x;
    const int warp = tid >> 5;
    const int lane = tid & 31;
    const int s0 = blockIdx.x * 128;
    const int j0 = blockIdx.y * 128;
    const int b  = blockIdx.z;

    const __half* Ap = Ax + (long long)b * K * HW;
    const long long obase = ((long long)b * OCtot + j0) * HW + s0;

    const int mbase = (warp >> 1) * 32;
    const int nbase = (warp & 1) * 64;

    float acc[64];
    #pragma unroll
    for (int i = 0; i < 64; i++) acc[i] = 0.f;

    const int lrow  = (lane & 7) + ((lane >> 3) & 1) * 8;
    const int lhalf = lane >> 4;

    const int wj = tid >> 2, wq = tid & 3;
    const int ak = tid >> 4, ag = tid & 15;

    auto stage = [&](int kc, int buf) {
        const uint32_t bW = uS + (uint32_t)(buf * BUFE) * 2;
        const uint32_t bA = bW + WTE * 2;
        const int k0 = kc * 32;
        #pragma unroll
        for (int i = 0; i < 2; i++) {
            int j = wj + i * 64;
            uint32_t d = (uint32_t)(j * WPITCH + wq * 8) * 2;
            cp16(bW + d, W + (long long)(j0 + j) * K + k0 + wq * 8);
        }
        #pragma unroll
        for (int i = 0; i < 2; i++) {
            int kk = ak + i * 16;
            uint32_t d = (uint32_t)(kk * APITCH + ag * 8) * 2;
            cp16(bA + d, Ap + (long long)(k0 + kk) * HW + s0 + ag * 8);
        }
        CP_COMMIT();
    };

    const int NK = K / 32;
    stage(0, 0);

    for (int kc = 0; kc < NK; kc++) {
        const int buf = kc & 1;
        if (kc + 1 < NK) {
            stage(kc + 1, (kc + 1) & 1);
            CP_WAIT1();
        } else {
            CP_WAIT0();
        }
        __syncthreads();

        const uint32_t bW = uS + (uint32_t)(buf * BUFE) * 2;
        const uint32_t bA = bW + WTE * 2;

        #pragma unroll
        for (int kh = 0; kh < 2; kh++) {
            uint32_t ah[2][4];
            #pragma unroll
            for (int mt = 0; mt < 2; mt++) {
                uint32_t off = (uint32_t)((mbase + mt * 16 + lrow) * (WPITCH * 2)
                                          + kh * 32 + lhalf * 16);
                ldsm_x4(ah[mt], bW + off);
            }
            #pragma unroll
            for (int np = 0; np < 4; np++) {
                uint32_t boff = (uint32_t)((kh * 16 + lrow) * (APITCH * 2)
                                           + (nbase + np * 16 + lhalf * 8) * 2);
                uint32_t bf[4];
                ldsm_x4_t(bf, bA + boff);
                #pragma unroll
                for (int nt2 = 0; nt2 < 2; nt2++) {
                    const uint32_t b0 = bf[nt2 * 2], b1 = bf[nt2 * 2 + 1];
                    const int nt = np * 2 + nt2;
                    #pragma unroll
                    for (int mt = 0; mt < 2; mt++)
                        mma_f16(acc + (mt * 8 + nt) * 4, ah[mt], b0, b1);
                }
            }
        }
        __syncthreads();
    }

    // ---- epilogue ----
    const int crow = lane >> 2;
    const int ccol = (lane & 3) * 2;
    #pragma unroll
    for (int mt = 0; mt < 2; mt++) {
        #pragma unroll
        for (int nt = 0; nt < 8; nt++) {
            const float* cp = acc + (mt * 8 + nt) * 4;
            long long r0 = obase + (long long)(mbase + mt * 16 + crow) * HW
                         + nbase + nt * 8 + ccol;
            long long r1 = r0 + 8 * HW;
            if (HALF_OUT) {
                *(uint32_t*)&Oh[r0] = pack_h2(cp[0], cp[1]);
                *(uint32_t*)&Oh[r1] = pack_h2(cp[2], cp[3]);
            } else {
                *(float2*)&Of[r0] = make_float2(cp[0], cp[1]);
                *(float2*)&Of[r1] = make_float2(cp[2], cp[3]);
            }
        }
    }
}

// ---------------------------------------------------------------------------
// qk_mma: S_partial = Q K^T over a 512-spatial slice (fp16 1-term MMA)
// + per-row sumsq partials (from the same rounded values the MMA uses).
// grid = (NCHUNK_QK, B*HD), 256 threads.
// ---------------------------------------------------------------------------
#define QKP 136
#define QK_ARR (48 * QKP)
#define QK_SMEM (2 * QK_ARR * 2)     // 26112 bytes

__global__ __launch_bounds__(256) void qk_mma_kernel(
    const __half* __restrict__ qh, const __half* __restrict__ kh,
    float* __restrict__ Sp, float* __restrict__ ssp)
{
    extern __shared__ __align__(16) uint16_t dynsmem[];
    __shared__ float Sred[DC][DC + 1];

    const uint32_t uQ = smem_u32(dynsmem);
    const uint32_t uK = uQ + QK_ARR * 2;

    const int chunk = blockIdx.x;
    const int bh = blockIdx.y;
    const int b  = bh >> 3;
    const int h  = bh & 7;
    const long long qbase = ((long long)b * C   + h * DC) * HW;
    const long long kbase = ((long long)b * KVC + h * DC) * HW;
    const int sbase = chunk * (HW / NCHUNK_QK);

    const int tid  = threadIdx.x;
    const int warp = tid >> 5;
    const int lane = tid & 31;
    const int lrow  = (lane & 7) + ((lane >> 3) & 1) * 8;
    const int lhalf = lane >> 4;
    const int brow = ((lane >> 4) << 3) + (lane & 7);
    const int bcol = ((lane >> 3) & 1) * 8;

    const int kcol = warp * 16;

    float acc[72];
    #pragma unroll
    for (int i = 0; i < 72; i++) acc[i] = 0.f;
    float ssq = 0.f;

    for (int it = 0; it < 4; it++) {
        const int s0 = sbase + it * 128;
        #pragma unroll
        for (int i = 0; i < 3; i++) {
            int idx = i * 256 + tid;
            int row = idx >> 4, g = idx & 15;
            uint32_t d = (uint32_t)(row * QKP + g * 8) * 2;
            cp16(uQ + d, qh + qbase + (long long)row * HW + s0 + g * 8);
            cp16(uK + d, kh + kbase + (long long)row * HW + s0 + g * 8);
        }
        CP_COMMIT();
        CP_WAIT0();
        __syncthreads();

        uint32_t bhf[12];
        #pragma unroll
        for (int g = 0; g < 3; g++) {
            uint32_t off = (uint32_t)((g * 16 + brow) * QKP + kcol + bcol) * 2;
            ldsm_x4(&bhf[g * 4], uK + off);
        }
        #pragma unroll
        for (int mt = 0; mt < 3; mt++) {
            uint32_t ah[4];
            uint32_t off = (uint32_t)((mt * 16 + lrow) * QKP + kcol + lhalf * 8) * 2;
            ldsm_x4(ah, uQ + off);
            #pragma unroll
            for (int n8 = 0; n8 < 6; n8++)
                mma_f16(acc + (mt * 6 + n8) * 4, ah, bhf[n8 * 2], bhf[n8 * 2 + 1]);
        }

        if (tid < 2 * DC) {
            const int r = (tid < DC) ? tid : tid - DC;
            const uint16_t* ph = (const uint16_t*)dynsmem
                               + (tid < DC ? 0 : QK_ARR) + r * QKP;
            #pragma unroll 8
            for (int g = 0; g < 64; g++) {
                uint32_t v = *(const uint32_t*)(ph + g * 2);
                float a = h_lo(v);
                float c = h_hi(v);
                ssq = fmaf(a, a, ssq);
                ssq = fmaf(c, c, ssq);
            }
        }
        __syncthreads();
    }

    for (int i = tid; i < DC * DC; i += 256) Sred[i / DC][i % DC] = 0.f;
    __syncthreads();
    const int crow = lane >> 2;
    const int ccol = (lane & 3) * 2;
    #pragma unroll
    for (int mt = 0; mt < 3; mt++) {
        #pragma unroll
        for (int n8 = 0; n8 < 6; n8++) {
            const float* cp = acc + (mt * 6 + n8) * 4;
            int r0 = mt * 16 + crow, c0 = n8 * 8 + ccol;
            atomicAdd(&Sred[r0][c0],     cp[0]);
            atomicAdd(&Sred[r0][c0 + 1], cp[1]);
            atomicAdd(&Sred[r0 + 8][c0],     cp[2]);
            atomicAdd(&Sred[r0 + 8][c0 + 1], cp[3]);
        }
    }
    __syncthreads();

    float* Sout = Sp + ((long long)chunk * (B * HD) + bh) * (DC * DC);
    for (int i = tid; i < DC * DC; i += 256)
        Sout[i] = Sred[i / DC][i % DC];
    if (tid < 2 * DC)
        ssp[((long long)chunk * (B * HD) + bh) * (2 * DC) + tid] = ssq;
}

// ---------------------------------------------------------------------------
// Reduce partials, norms + temperature, softmax; write S as fp16 (1-limb).
// ---------------------------------------------------------------------------
__global__ __launch_bounds__(256) void softmax_kernel(
    const float* __restrict__ Sp, const float* __restrict__ ssp,
    const float* __restrict__ temperature,
    __half* __restrict__ ShG)
{
    const int bh = blockIdx.x;
    const int h  = bh & 7;
    const int tid = threadIdx.x;

    __shared__ float S[DC][DC + 1];
    __shared__ float invq[DC], invk[DC];

    for (int i = tid; i < DC * DC; i += 256) {
        float s = 0.f;
        #pragma unroll
        for (int ch = 0; ch < NCHUNK_QK; ch++)
            s += Sp[((long long)ch * (B * HD) + bh) * (DC * DC) + i];
        S[i / DC][i % DC] = s;
    }
    if (tid < 2 * DC) {
        float s = 0.f;
        #pragma unroll
        for (int ch = 0; ch < NCHUNK_QK; ch++)
            s += ssp[((long long)ch * (B * HD) + bh) * (2 * DC) + tid];
        float inv = 1.0f / fmaxf(sqrtf(s), 1e-12f);
        if (tid < DC) invq[tid] = inv; else invk[tid - DC] = inv;
    }
    __syncthreads();

    if (tid < DC) {
        const float t = temperature[h];
        const float iq = invq[tid] * t;
        float m = -INFINITY;
        float row[DC];
        #pragma unroll 8
        for (int d = 0; d < DC; d++) {
            float v = S[tid][d] * iq * invk[d];
            row[d] = v;
            m = fmaxf(m, v);
        }
        float sum = 0.f;
        #pragma unroll 8
        for (int d = 0; d < DC; d++) {
            float e = expf(row[d] - m);
            row[d] = e;
            sum += e;
        }
        float inv = 1.0f / sum;
        uint32_t* oh = (uint32_t*)(ShG + (long long)bh * (DC * DC) + tid * DC);
        #pragma unroll
        for (int d = 0; d < DC; d += 2)
            oh[d / 2] = pack_h2(row[d] * inv, row[d + 1] * inv);
    }
}

// ---------------------------------------------------------------------------
// sv_mma: O = S * V (fp16 1-term, K=48). Writes oh for GEMM3.
// grid = (NCHUNK_SV, B*HD).
// ---------------------------------------------------------------------------
#define SPITCH 56
#define VPITCH 136

__global__ __launch_bounds__(256) void sv_mma_kernel(
    const __half* __restrict__ ShG,
    const __half* __restrict__ vh,
    __half* __restrict__ oh)
{
    __shared__ __align__(16) uint16_t sS[DC * SPITCH];
    __shared__ __align__(16) uint16_t sV[DC * VPITCH];

    const int chunk = blockIdx.x;
    const int bh = blockIdx.y;
    const int b  = bh >> 3;
    const int h  = bh & 7;
    const long long vbase = ((long long)b * KVC + C + h * DC) * HW;
    const long long obase = ((long long)b * C + h * DC) * HW;
    const int sbase = chunk * (HW / NCHUNK_SV);

    const int tid  = threadIdx.x;
    const int warp = tid >> 5;
    const int lane = tid & 31;
    const int lrow  = (lane & 7) + ((lane >> 3) & 1) * 8;
    const int lhalf = lane >> 4;
    const int crow = lane >> 2;
    const int ccol = (lane & 3) * 2;

    const uint32_t uS = smem_u32(sS);
    const uint32_t uV = smem_u32(sV);

    for (int idx = tid; idx < 288; idx += 256) {
        int row = idx / 6, g = idx % 6;
        uint32_t d = (uint32_t)(row * SPITCH + g * 8) * 2;
        cp16(uS + d, ShG + (long long)bh * (DC * DC) + row * DC + g * 8);
    }

    const int n0w = warp * 16;

    for (int it = 0; it < 2; it++) {
        const int s0 = sbase + it * 128;
        #pragma unroll
        for (int i = 0; i < 3; i++) {
            int idx = i * 256 + tid;
            int row = idx >> 4, g = idx & 15;
            uint32_t d = (uint32_t)(row * VPITCH + g * 8) * 2;
            cp16(uV + d, vh + vbase + (long long)row * HW + s0 + g * 8);
        }
        CP_COMMIT();
        CP_WAIT0();
        __syncthreads();

        float acc[24];
        #pragma unroll
        for (int i = 0; i < 24; i++) acc[i] = 0.f;

        #pragma unroll
        for (int ks = 0; ks < 3; ks++) {
            uint32_t bhf[4];
            uint32_t boff = (uint32_t)((ks * 16 + lrow) * VPITCH
                                       + n0w + lhalf * 8) * 2;
            ldsm_x4_t(bhf, uV + boff);
            #pragma unroll
            for (int mt = 0; mt < 3; mt++) {
                uint32_t ah[4];
                uint32_t aoff = (uint32_t)((mt * 16 + lrow) * SPITCH
                                           + ks * 16 + lhalf * 8) * 2;
                ldsm_x4(ah, uS + aoff);
                #pragma unroll
                for (int nt2 = 0; nt2 < 2; nt2++)
                    mma_f16(acc + (mt * 2 + nt2) * 4, ah,
                            bhf[nt2 * 2], bhf[nt2 * 2 + 1]);
            }
        }

        #pragma unroll
        for (int mt = 0; mt < 3; mt++) {
            #pragma unroll
            for (int nt2 = 0; nt2 < 2; nt2++) {
                const float* cp = acc + (mt * 2 + nt2) * 4;
                int cc = mt * 16 + crow;
                int ss = s0 + n0w + nt2 * 8 + ccol;
                long long r0 = obase + (long long)cc * HW + ss;
                long long r1 = r0 + 8 * HW;
                *(uint32_t*)&oh[r0] = pack_h2(cp[0], cp[1]);
                *(uint32_t*)&oh[r1] = pack_h2(cp[2], cp[3]);
            }
        }
        __syncthreads();
    }
}

// ---------------------------------------------------------------------------
// Launch
// ---------------------------------------------------------------------------
extern "C" void kernel_launch(void* const* d_in, const int* in_sizes, int n_in,
                              void* d_out, int out_size)
{
    const float* x           = (const float*)d_in[0];
    const float* query       = (const float*)d_in[1];
    const float* w_kv        = (const float*)d_in[2];
    const float* w_q         = (const float*)d_in[3];
    const float* w_proj      = (const float*)d_in[4];
    const float* temperature = (const float*)d_in[5];
    float* out = (float*)d_out;

    float *Sp, *ssp;
    cudaGetSymbolAddress((void**)&Sp,  g_Sp);
    cudaGetSymbolAddress((void**)&ssp, g_ssp);

    __half *wkv, *wq, *wp, *xh, *qrh, *kvh, *qh, *oh, *Sh;
    cudaGetSymbolAddress((void**)&wkv,  g_wkv);
    cudaGetSymbolAddress((void**)&wq,   g_wq);
    cudaGetSymbolAddress((void**)&wp,   g_wp);
    cudaGetSymbolAddress((void**)&xh,   g_xh);
    cudaGetSymbolAddress((void**)&qrh,  g_qrh);
    cudaGetSymbolAddress((void**)&kvh,  g_kvh);
    cudaGetSymbolAddress((void**)&qh,   g_qh);
    cudaGetSymbolAddress((void**)&oh,   g_oh);
    cudaGetSymbolAddress((void**)&Sh,   g_Sh);

    cudaFuncSetAttribute(gemm_db_kernel<C, true>,
                         cudaFuncAttributeMaxDynamicSharedMemorySize, SMEM_BYTES);
    cudaFuncSetAttribute(gemm_db_kernel<QC, true>,
                         cudaFuncAttributeMaxDynamicSharedMemorySize, SMEM_BYTES);
    cudaFuncSetAttribute(gemm_db_kernel<C, false>,
                         cudaFuncAttributeMaxDynamicSharedMemorySize, SMEM_BYTES);
    cudaFuncSetAttribute(qk_mma_kernel,
                         cudaFuncAttributeMaxDynamicSharedMemorySize, QK_SMEM);

    // 0) fp32 -> fp16 conversions
    {
        int n4;
        n4 = KVC * C / 4;
        split1_kernel<<<(n4 + 255) / 256, 256>>>(w_kv, wkv, n4);
        n4 = C * QC / 4;
        split1_kernel<<<(n4 + 255) / 256, 256>>>(w_q, wq, n4);
        n4 = C * C / 4;
        split1_kernel<<<(n4 + 255) / 256, 256>>>(w_proj, wp, n4);
        n4 = (int)((long long)B * C * HW / 4);
        split1_kernel<<<(n4 + 255) / 256, 256>>>(x, xh, n4);
        n4 = (int)((long long)B * QC * HW / 4);
        split1_kernel<<<(n4 + 255) / 256, 256>>>(query, qrh, n4);
    }

    // 1) kv = w_kv @ x  -> fp16
    gemm_db_kernel<C, true><<<dim3(HW / 128, KVC / 128, B), 256, SMEM_BYTES>>>(
        wkv, xh, nullptr, kvh, KVC);

    // 2) q = w_q @ query -> fp16
    gemm_db_kernel<QC, true><<<dim3(HW / 128, C / 128, B), 256, SMEM_BYTES>>>(
        wq, qrh, nullptr, qh, C);

    // 3) QK^T partials + sumsq (1-term fp16 MMA)
    qk_mma_kernel<<<dim3(NCHUNK_QK, B * HD), 256, QK_SMEM>>>(
        qh, kvh, Sp, ssp);

    // 4) reduce + norm-scale + softmax -> S fp16
    softmax_kernel<<<B * HD, 256>>>(Sp, ssp, temperature, Sh);

    // 5) O = S * V (1-term fp16 MMA) -> fp16
    sv_mma_kernel<<<dim3(NCHUNK_SV, B * HD), 256>>>(Sh, kvh, oh);

    // 6) out = w_proj @ o -> fp32
    gemm_db_kernel<C, false><<<dim3(HW / 128, C / 128, B), 256, SMEM_BYTES>>>(
        wp, oh, out, nullptr, C);
}

// round 16
// speedup vs baseline: 2.5377x; 1.0557x over previous
#include <cuda_runtime.h>
#include <cuda_fp16.h>
#include <math.h>
#include <stdint.h>

// Problem constants
#define B   16
#define C   384
#define HD  8
#define DC  48
#define HW  4096
#define QC  192
#define KVC 768

#define NCHUNK_QK 8
#define NCHUNK_SV 16

// Scratch (device globals)
__device__ float g_Sp [NCHUNK_QK * B * HD * DC * DC];
__device__ float g_ssp[NCHUNK_QK * B * HD * 2 * DC];

// fp16 operand buffers (ALL 1-limb)
__device__ __half g_wkv[KVC * C];
__device__ __half g_wq [C * QC];
__device__ __half g_wp [C * C];
__device__ __half g_xh [(long long)B * C  * HW];
__device__ __half g_qrh[(long long)B * QC * HW];
__device__ __half g_kvh[(long long)B * KVC * HW];
__device__ __half g_qh [(long long)B * C  * HW];
__device__ __half g_oh [(long long)B * C  * HW];
__device__ __half g_Sh [B * HD * DC * DC];

// ---------------------------------------------------------------------------
// PTX helpers
// ---------------------------------------------------------------------------
__device__ __forceinline__ uint32_t smem_u32(const void* p) {
    uint32_t a;
    asm("{ .reg .u64 t; cvta.to.shared.u64 t, %1; cvt.u32.u64 %0, t; }" : "=r"(a) : "l"(p));
    return a;
}
__device__ __forceinline__ void cp16(uint32_t dst, const void* src) {
    asm volatile("cp.async.ca.shared.global [%0], [%1], 16;" :: "r"(dst), "l"(src));
}
#define CP_COMMIT() asm volatile("cp.async.commit_group;" ::: "memory")
#define CP_WAIT0()  asm volatile("cp.async.wait_group 0;" ::: "memory")
#define CP_WAIT1()  asm volatile("cp.async.wait_group 1;" ::: "memory")

__device__ __forceinline__ void ldsm_x4(uint32_t r[4], uint32_t addr) {
    asm volatile("ldmatrix.sync.aligned.m8n8.x4.shared.b16 {%0,%1,%2,%3}, [%4];"
                 : "=r"(r[0]), "=r"(r[1]), "=r"(r[2]), "=r"(r[3]) : "r"(addr));
}
__device__ __forceinline__ void ldsm_x4_t(uint32_t r[4], uint32_t addr) {
    asm volatile("ldmatrix.sync.aligned.m8n8.x4.trans.shared.b16 {%0,%1,%2,%3}, [%4];"
                 : "=r"(r[0]), "=r"(r[1]), "=r"(r[2]), "=r"(r[3]) : "r"(addr));
}
__device__ __forceinline__ void mma_f16(float* c, const uint32_t a[4],
                                        uint32_t b0, uint32_t b1) {
    asm volatile(
        "mma.sync.aligned.m16n8k16.row.col.f32.f16.f16.f32 "
        "{%0,%1,%2,%3}, {%4,%5,%6,%7}, {%8,%9}, {%0,%1,%2,%3};"
        : "+f"(c[0]), "+f"(c[1]), "+f"(c[2]), "+f"(c[3])
        : "r"(a[0]), "r"(a[1]), "r"(a[2]), "r"(a[3]), "r"(b0), "r"(b1));
}

__device__ __forceinline__ uint32_t pack_h2(float x0, float x1) {
    return (uint32_t)__half_as_ushort(__float2half_rn(x0))
         | ((uint32_t)__half_as_ushort(__float2half_rn(x1)) << 16);
}
__device__ __forceinline__ float h_lo(uint32_t v) {
    return __half2float(__ushort_as_half((uint16_t)v));
}
__device__ __forceinline__ float h_hi(uint32_t v) {
    return __half2float(__ushort_as_half((uint16_t)(v >> 16)));
}

// fp32 -> fp16 (round-to-nearest), 4 elems/thread
__global__ __launch_bounds__(256) void split1_kernel(
    const float* __restrict__ src, __half* __restrict__ dh, int n4)
{
    int i = blockIdx.x * 256 + threadIdx.x;
    if (i < n4) {
        float4 v = ((const float4*)src)[i];
        ((uint2*)dh)[i] = make_uint2(pack_h2(v.x, v.y), pack_h2(v.z, v.w));
    }
}

// ---------------------------------------------------------------------------
// fp16 1-term tensor-core GEMM: Out[b][j][s] = sum_k W[j][k] * Act[b][k][s]
// CTA tile 128(j) x 128(s), K-chunk 64, 8 warps (4m x 2n), double-buffered.
// HALF_OUT: write fp16 (Oh) else fp32 (Of).
// ---------------------------------------------------------------------------
#define WPITCH 72                    // 64 + 8 pad (144B rows, conflict-free ldsm)
#define APITCH 136
#define WTE (128 * WPITCH)           // 9216
#define ATE (64 * APITCH)            // 8704
#define BUFE (WTE + ATE)             // 17920
#define SMEM_BYTES (2 * BUFE * 2)    // 71680 bytes

template<int K, bool HALF_OUT>
__global__ __launch_bounds__(256, 2) void gemm_db_kernel(
    const __half* __restrict__ W,
    const __half* __restrict__ Ax,
    float* __restrict__ Of,
    __half* __restrict__ Oh,
    int OCtot)
{
    extern __shared__ __align__(16) uint16_t dynsmem[];
    const uint32_t uS = smem_u32(dynsmem);

    const int tid  = threadIdx.x;
    const int warp = tid >> 5;
    const int lane = tid & 31;
    const int s0 = blockIdx.x * 128;
    const int j0 = blockIdx.y * 128;
    const int b  = blockIdx.z;

    const __half* Ap = Ax + (long long)b * K * HW;
    const long long obase = ((long long)b * OCtot + j0) * HW + s0;

    const int mbase = (warp >> 1) * 32;
    const int nbase = (warp & 1) * 64;

    float acc[64];
    #pragma unroll
    for (int i = 0; i < 64; i++) acc[i] = 0.f;

    const int lrow  = (lane & 7) + ((lane >> 3) & 1) * 8;
    const int lhalf = lane >> 4;

    auto stage = [&](int kc, int buf) {
        const uint32_t bW = uS + (uint32_t)(buf * BUFE) * 2;
        const uint32_t bA = bW + WTE * 2;
        const int k0 = kc * 64;
        // W tile: 128 j x 64 k = 1024 x 16B, 4 cp16/thread
        #pragma unroll
        for (int i = 0; i < 4; i++) {
            int idx = i * 256 + tid;
            int j = idx >> 3, q = idx & 7;
            uint32_t d = (uint32_t)(j * WPITCH + q * 8) * 2;
            cp16(bW + d, W + (long long)(j0 + j) * K + k0 + q * 8);
        }
        // A tile: 64 k x 128 s = 1024 x 16B, 4 cp16/thread
        #pragma unroll
        for (int i = 0; i < 4; i++) {
            int idx = i * 256 + tid;
            int kk = idx >> 4, g = idx & 15;
            uint32_t d = (uint32_t)(kk * APITCH + g * 8) * 2;
            cp16(bA + d, Ap + (long long)(k0 + kk) * HW + s0 + g * 8);
        }
        CP_COMMIT();
    };

    const int NK = K / 64;
    stage(0, 0);

    for (int kc = 0; kc < NK; kc++) {
        const int buf = kc & 1;
        if (kc + 1 < NK) {
            stage(kc + 1, (kc + 1) & 1);
            CP_WAIT1();
        } else {
            CP_WAIT0();
        }
        __syncthreads();

        const uint32_t bW = uS + (uint32_t)(buf * BUFE) * 2;
        const uint32_t bA = bW + WTE * 2;

        #pragma unroll
        for (int kh = 0; kh < 4; kh++) {
            uint32_t ah[2][4];
            #pragma unroll
            for (int mt = 0; mt < 2; mt++) {
                uint32_t off = (uint32_t)((mbase + mt * 16 + lrow) * (WPITCH * 2)
                                          + kh * 32 + lhalf * 16);
                ldsm_x4(ah[mt], bW + off);
            }
            #pragma unroll
            for (int np = 0; np < 4; np++) {
                uint32_t boff = (uint32_t)((kh * 16 + lrow) * (APITCH * 2)
                                           + (nbase + np * 16 + lhalf * 8) * 2);
                uint32_t bf[4];
                ldsm_x4_t(bf, bA + boff);
                #pragma unroll
                for (int nt2 = 0; nt2 < 2; nt2++) {
                    const uint32_t b0 = bf[nt2 * 2], b1 = bf[nt2 * 2 + 1];
                    const int nt = np * 2 + nt2;
                    #pragma unroll
                    for (int mt = 0; mt < 2; mt++)
                        mma_f16(acc + (mt * 8 + nt) * 4, ah[mt], b0, b1);
                }
            }
        }
        __syncthreads();
    }

    // ---- epilogue ----
    const int crow = lane >> 2;
    const int ccol = (lane & 3) * 2;
    #pragma unroll
    for (int mt = 0; mt < 2; mt++) {
        #pragma unroll
        for (int nt = 0; nt < 8; nt++) {
            const float* cp = acc + (mt * 8 + nt) * 4;
            long long r0 = obase + (long long)(mbase + mt * 16 + crow) * HW
                         + nbase + nt * 8 + ccol;
            long long r1 = r0 + 8 * HW;
            if (HALF_OUT) {
                *(uint32_t*)&Oh[r0] = pack_h2(cp[0], cp[1]);
                *(uint32_t*)&Oh[r1] = pack_h2(cp[2], cp[3]);
            } else {
                *(float2*)&Of[r0] = make_float2(cp[0], cp[1]);
                *(float2*)&Of[r1] = make_float2(cp[2], cp[3]);
            }
        }
    }
}

// ---------------------------------------------------------------------------
// qk_mma: S_partial = Q K^T over a 512-spatial slice (fp16 1-term MMA)
// + per-row sumsq partials (from the same rounded values the MMA uses).
// grid = (NCHUNK_QK, B*HD), 256 threads.
// ---------------------------------------------------------------------------
#define QKP 136
#define QK_ARR (48 * QKP)
#define QK_SMEM (2 * QK_ARR * 2)     // 26112 bytes

__global__ __launch_bounds__(256) void qk_mma_kernel(
    const __half* __restrict__ qh, const __half* __restrict__ kh,
    float* __restrict__ Sp, float* __restrict__ ssp)
{
    extern __shared__ __align__(16) uint16_t dynsmem[];
    __shared__ float Sred[DC][DC + 1];

    const uint32_t uQ = smem_u32(dynsmem);
    const uint32_t uK = uQ + QK_ARR * 2;

    const int chunk = blockIdx.x;
    const int bh = blockIdx.y;
    const int b  = bh >> 3;
    const int h  = bh & 7;
    const long long qbase = ((long long)b * C   + h * DC) * HW;
    const long long kbase = ((long long)b * KVC + h * DC) * HW;
    const int sbase = chunk * (HW / NCHUNK_QK);

    const int tid  = threadIdx.x;
    const int warp = tid >> 5;
    const int lane = tid & 31;
    const int lrow  = (lane & 7) + ((lane >> 3) & 1) * 8;
    const int lhalf = lane >> 4;
    const int brow = ((lane >> 4) << 3) + (lane & 7);
    const int bcol = ((lane >> 3) & 1) * 8;

    const int kcol = warp * 16;

    float acc[72];
    #pragma unroll
    for (int i = 0; i < 72; i++) acc[i] = 0.f;
    float ssq = 0.f;

    for (int it = 0; it < 4; it++) {
        const int s0 = sbase + it * 128;
        #pragma unroll
        for (int i = 0; i < 3; i++) {
            int idx = i * 256 + tid;
            int row = idx >> 4, g = idx & 15;
            uint32_t d = (uint32_t)(row * QKP + g * 8) * 2;
            cp16(uQ + d, qh + qbase + (long long)row * HW + s0 + g * 8);
            cp16(uK + d, kh + kbase + (long long)row * HW + s0 + g * 8);
        }
        CP_COMMIT();
        CP_WAIT0();
        __syncthreads();

        uint32_t bhf[12];
        #pragma unroll
        for (int g = 0; g < 3; g++) {
            uint32_t off = (uint32_t)((g * 16 + brow) * QKP + kcol + bcol) * 2;
            ldsm_x4(&bhf[g * 4], uK + off);
        }
        #pragma unroll
        for (int mt = 0; mt < 3; mt++) {
            uint32_t ah[4];
            uint32_t off = (uint32_t)((mt * 16 + lrow) * QKP + kcol + lhalf * 8) * 2;
            ldsm_x4(ah, uQ + off);
            #pragma unroll
            for (int n8 = 0; n8 < 6; n8++)
                mma_f16(acc + (mt * 6 + n8) * 4, ah, bhf[n8 * 2], bhf[n8 * 2 + 1]);
        }

        if (tid < 2 * DC) {
            const int r = (tid < DC) ? tid : tid - DC;
            const uint16_t* ph = (const uint16_t*)dynsmem
                               + (tid < DC ? 0 : QK_ARR) + r * QKP;
            #pragma unroll 8
            for (int g = 0; g < 64; g++) {
                uint32_t v = *(const uint32_t*)(ph + g * 2);
                float a = h_lo(v);
                float c = h_hi(v);
                ssq = fmaf(a, a, ssq);
                ssq = fmaf(c, c, ssq);
            }
        }
        __syncthreads();
    }

    for (int i = tid; i < DC * DC; i += 256) Sred[i / DC][i % DC] = 0.f;
    __syncthreads();
    const int crow = lane >> 2;
    const int ccol = (lane & 3) * 2;
    #pragma unroll
    for (int mt = 0; mt < 3; mt++) {
        #pragma unroll
        for (int n8 = 0; n8 < 6; n8++) {
            const float* cp = acc + (mt * 6 + n8) * 4;
            int r0 = mt * 16 + crow, c0 = n8 * 8 + ccol;
            atomicAdd(&Sred[r0][c0],     cp[0]);
            atomicAdd(&Sred[r0][c0 + 1], cp[1]);
            atomicAdd(&Sred[r0 + 8][c0],     cp[2]);
            atomicAdd(&Sred[r0 + 8][c0 + 1], cp[3]);
        }
    }
    __syncthreads();

    float* Sout = Sp + ((long long)chunk * (B * HD) + bh) * (DC * DC);
    for (int i = tid; i < DC * DC; i += 256)
        Sout[i] = Sred[i / DC][i % DC];
    if (tid < 2 * DC)
        ssp[((long long)chunk * (B * HD) + bh) * (2 * DC) + tid] = ssq;
}

// ---------------------------------------------------------------------------
// Reduce partials, norms + temperature, softmax; write S as fp16 (1-limb).
// ---------------------------------------------------------------------------
__global__ __launch_bounds__(256) void softmax_kernel(
    const float* __restrict__ Sp, const float* __restrict__ ssp,
    const float* __restrict__ temperature,
    __half* __restrict__ ShG)
{
    const int bh = blockIdx.x;
    const int h  = bh & 7;
    const int tid = threadIdx.x;

    __shared__ float S[DC][DC + 1];
    __shared__ float invq[DC], invk[DC];

    for (int i = tid; i < DC * DC; i += 256) {
        float s = 0.f;
        #pragma unroll
        for (int ch = 0; ch < NCHUNK_QK; ch++)
            s += Sp[((long long)ch * (B * HD) + bh) * (DC * DC) + i];
        S[i / DC][i % DC] = s;
    }
    if (tid < 2 * DC) {
        float s = 0.f;
        #pragma unroll
        for (int ch = 0; ch < NCHUNK_QK; ch++)
            s += ssp[((long long)ch * (B * HD) + bh) * (2 * DC) + tid];
        float inv = 1.0f / fmaxf(sqrtf(s), 1e-12f);
        if (tid < DC) invq[tid] = inv; else invk[tid - DC] = inv;
    }
    __syncthreads();

    if (tid < DC) {
        const float t = temperature[h];
        const float iq = invq[tid] * t;
        float m = -INFINITY;
        float row[DC];
        #pragma unroll 8
        for (int d = 0; d < DC; d++) {
            float v = S[tid][d] * iq * invk[d];
            row[d] = v;
            m = fmaxf(m, v);
        }
        float sum = 0.f;
        #pragma unroll 8
        for (int d = 0; d < DC; d++) {
            float e = expf(row[d] - m);
            row[d] = e;
            sum += e;
        }
        float inv = 1.0f / sum;
        uint32_t* oh = (uint32_t*)(ShG + (long long)bh * (DC * DC) + tid * DC);
        #pragma unroll
        for (int d = 0; d < DC; d += 2)
            oh[d / 2] = pack_h2(row[d] * inv, row[d + 1] * inv);
    }
}

// ---------------------------------------------------------------------------
// sv_mma: O = S * V (fp16 1-term, K=48). Writes oh for GEMM3.
// grid = (NCHUNK_SV, B*HD).
// ---------------------------------------------------------------------------
#define SPITCH 56
#define VPITCH 136

__global__ __launch_bounds__(256) void sv_mma_kernel(
    const __half* __restrict__ ShG,
    const __half* __restrict__ vh,
    __half* __restrict__ oh)
{
    __shared__ __align__(16) uint16_t sS[DC * SPITCH];
    __shared__ __align__(16) uint16_t sV[DC * VPITCH];

    const int chunk = blockIdx.x;
    const int bh = blockIdx.y;
    const int b  = bh >> 3;
    const int h  = bh & 7;
    const long long vbase = ((long long)b * KVC + C + h * DC) * HW;
    const long long obase = ((long long)b * C + h * DC) * HW;
    const int sbase = chunk * (HW / NCHUNK_SV);

    const int tid  = threadIdx.x;
    const int warp = tid >> 5;
    const int lane = tid & 31;
    const int lrow  = (lane & 7) + ((lane >> 3) & 1) * 8;
    const int lhalf = lane >> 4;
    const int crow = lane >> 2;
    const int ccol = (lane & 3) * 2;

    const uint32_t uS = smem_u32(sS);
    const uint32_t uV = smem_u32(sV);

    for (int idx = tid; idx < 288; idx += 256) {
        int row = idx / 6, g = idx % 6;
        uint32_t d = (uint32_t)(row * SPITCH + g * 8) * 2;
        cp16(uS + d, ShG + (long long)bh * (DC * DC) + row * DC + g * 8);
    }

    const int n0w = warp * 16;

    for (int it = 0; it < 2; it++) {
        const int s0 = sbase + it * 128;
        #pragma unroll
        for (int i = 0; i < 3; i++) {
            int idx = i * 256 + tid;
            int row = idx >> 4, g = idx & 15;
            uint32_t d = (uint32_t)(row * VPITCH + g * 8) * 2;
            cp16(uV + d, vh + vbase + (long long)row * HW + s0 + g * 8);
        }
        CP_COMMIT();
        CP_WAIT0();
        __syncthreads();

        float acc[24];
        #pragma unroll
        for (int i = 0; i < 24; i++) acc[i] = 0.f;

        #pragma unroll
        for (int ks = 0; ks < 3; ks++) {
            uint32_t bhf[4];
            uint32_t boff = (uint32_t)((ks * 16 + lrow) * VPITCH
                                       + n0w + lhalf * 8) * 2;
            ldsm_x4_t(bhf, uV + boff);
            #pragma unroll
            for (int mt = 0; mt < 3; mt++) {
                uint32_t ah[4];
                uint32_t aoff = (uint32_t)((mt * 16 + lrow) * SPITCH
                                           + ks * 16 + lhalf * 8) * 2;
                ldsm_x4(ah, uS + aoff);
                #pragma unroll
                for (int nt2 = 0; nt2 < 2; nt2++)
                    mma_f16(acc + (mt * 2 + nt2) * 4, ah,
                            bhf[nt2 * 2], bhf[nt2 * 2 + 1]);
            }
        }

        #pragma unroll
        for (int mt = 0; mt < 3; mt++) {
            #pragma unroll
            for (int nt2 = 0; nt2 < 2; nt2++) {
                const float* cp = acc + (mt * 2 + nt2) * 4;
                int cc = mt * 16 + crow;
                int ss = s0 + n0w + nt2 * 8 + ccol;
                long long r0 = obase + (long long)cc * HW + ss;
                long long r1 = r0 + 8 * HW;
                *(uint32_t*)&oh[r0] = pack_h2(cp[0], cp[1]);
                *(uint32_t*)&oh[r1] = pack_h2(cp[2], cp[3]);
            }
        }
        __syncthreads();
    }
}

// ---------------------------------------------------------------------------
// Launch
// ---------------------------------------------------------------------------
extern "C" void kernel_launch(void* const* d_in, const int* in_sizes, int n_in,
                              void* d_out, int out_size)
{
    const float* x           = (const float*)d_in[0];
    const float* query       = (const float*)d_in[1];
    const float* w_kv        = (const float*)d_in[2];
    const float* w_q         = (const float*)d_in[3];
    const float* w_proj      = (const float*)d_in[4];
    const float* temperature = (const float*)d_in[5];
    float* out = (float*)d_out;

    float *Sp, *ssp;
    cudaGetSymbolAddress((void**)&Sp,  g_Sp);
    cudaGetSymbolAddress((void**)&ssp, g_ssp);

    __half *wkv, *wq, *wp, *xh, *qrh, *kvh, *qh, *oh, *Sh;
    cudaGetSymbolAddress((void**)&wkv,  g_wkv);
    cudaGetSymbolAddress((void**)&wq,   g_wq);
    cudaGetSymbolAddress((void**)&wp,   g_wp);
    cudaGetSymbolAddress((void**)&xh,   g_xh);
    cudaGetSymbolAddress((void**)&qrh,  g_qrh);
    cudaGetSymbolAddress((void**)&kvh,  g_kvh);
    cudaGetSymbolAddress((void**)&qh,   g_qh);
    cudaGetSymbolAddress((void**)&oh,   g_oh);
    cudaGetSymbolAddress((void**)&Sh,   g_Sh);

    cudaFuncSetAttribute(gemm_db_kernel<C, true>,
                         cudaFuncAttributeMaxDynamicSharedMemorySize, SMEM_BYTES);
    cudaFuncSetAttribute(gemm_db_kernel<QC, true>,
                         cudaFuncAttributeMaxDynamicSharedMemorySize, SMEM_BYTES);
    cudaFuncSetAttribute(gemm_db_kernel<C, false>,
                         cudaFuncAttributeMaxDynamicSharedMemorySize, SMEM_BYTES);
    cudaFuncSetAttribute(qk_mma_kernel,
                         cudaFuncAttributeMaxDynamicSharedMemorySize, QK_SMEM);

    // 0) fp32 -> fp16 conversions
    {
        int n4;
        n4 = KVC * C / 4;
        split1_kernel<<<(n4 + 255) / 256, 256>>>(w_kv, wkv, n4);
        n4 = C * QC / 4;
        split1_kernel<<<(n4 + 255) / 256, 256>>>(w_q, wq, n4);
        n4 = C * C / 4;
        split1_kernel<<<(n4 + 255) / 256, 256>>>(w_proj, wp, n4);
        n4 = (int)((long long)B * C * HW / 4);
        split1_kernel<<<(n4 + 255) / 256, 256>>>(x, xh, n4);
        n4 = (int)((long long)B * QC * HW / 4);
        split1_kernel<<<(n4 + 255) / 256, 256>>>(query, qrh, n4);
    }

    // 1) kv = w_kv @ x  -> fp16
    gemm_db_kernel<C, true><<<dim3(HW / 128, KVC / 128, B), 256, SMEM_BYTES>>>(
        wkv, xh, nullptr, kvh, KVC);

    // 2) q = w_q @ query -> fp16
    gemm_db_kernel<QC, true><<<dim3(HW / 128, C / 128, B), 256, SMEM_BYTES>>>(
        wq, qrh, nullptr, qh, C);

    // 3) QK^T partials + sumsq (1-term fp16 MMA)
    qk_mma_kernel<<<dim3(NCHUNK_QK, B * HD), 256, QK_SMEM>>>(
        qh, kvh, Sp, ssp);

    // 4) reduce + norm-scale + softmax -> S fp16
    softmax_kernel<<<B * HD, 256>>>(Sp, ssp, temperature, Sh);

    // 5) O = S * V (1-term fp16 MMA) -> fp16
    sv_mma_kernel<<<dim3(NCHUNK_SV, B * HD), 256>>>(Sh, kvh, oh);

    // 6) out = w_proj @ o -> fp32
    gemm_db_kernel<C, false><<<dim3(HW / 128, C / 128, B), 256, SMEM_BYTES>>>(
        wp, oh, out, nullptr, C);
}